// round 8
// baseline (speedup 1.0000x reference)
#include <cuda_runtime.h>
#include <cuda_bf16.h>
#include <cstdint>

// ============================================================================
// EinetMixture: route each row to nearest centroid (E=8), then compute only
// that expert's Gaussian-leaf log-likelihood (K=64 leaves) + logsumexp.
//
// leaf_ll[b,k] = sum_d ( a[e,k,d]*x^2 + b[e,k,d]*x ) + c[e,k]
// d-reduction = bf16 mma.sync GEMM; K-dim interleaved as (x[d], x^2[d]) pairs
// matching W pairs (bcoef, acoef). (tcgen05 unavailable: bench targets sm_100.)
//
// Launches: k0 prep -> k1 route -> k3 scatter -> k4 grouped GEMM.
// ============================================================================

#define B_N 32768
#define D_N 784
#define D_PAD 800             // 25 chunks of 32 d (pad coeffs are zero)
#define E_N 8
#define K_N 64
#define F4_PER_ROW 196        // 784/4

#define TILE_M 128
#define CHUNK_D 32            // d's per K4 chunk (64 bf16 of K)
#define NCHUNK 25
#define KSTEPS 4              // k16 steps per chunk
#define A_PITCH 36            // u32 pitch; frag banks (4g+tig) distinct
#define B_PITCH 72            // u32 pitch; frag banks (8tig+g) distinct
#define C_PITCH 66            // float pitch for epilogue

#define A_BUF_BYTES (TILE_M * A_PITCH * 4)      // 18432
#define B_BUF_BYTES (CHUNK_D * B_PITCH * 4)     // 9216
#define SM_B_OFF   (2 * A_BUF_BYTES)            // 36864
#define SM_IDX_OFF (SM_B_OFF + 2 * B_BUF_BYTES) // 55296
#define SM_CC_OFF  (SM_IDX_OFF + TILE_M * 4)    // 55808
#define SM_TOTAL_K4 (SM_CC_OFF + K_N * 4)       // 56064

#define LOG_2PI 1.8378770664093453f

// ---------------- device scratch (no allocation allowed) ----------------
__device__ __align__(16) uint32_t d_Wpack[E_N * D_PAD * K_N]; // [e][d][k] bf16x2 (b,a)
__device__ float    d_ccomb[E_N * K_N];         // c + log_softmax(logits)
__device__ float    d_cnorm[E_N];
__device__ int      d_cluster[B_N];
__device__ int      d_counts[E_N];
__device__ int      d_cursor[E_N];
__device__ int      d_sortedIdx[B_N];

// ---------------- helpers ----------------
__device__ __forceinline__ uint32_t pack_x_x2(float v) {
    __nv_bfloat162 p = __floats2bfloat162_rn(v, v * v);   // lo = x, hi = x^2
    return *reinterpret_cast<uint32_t*>(&p);
}

__device__ __forceinline__ void mma_bf16(float* c, const uint32_t* a,
                                         uint32_t b0, uint32_t b1) {
    asm volatile(
        "mma.sync.aligned.m16n8k16.row.col.f32.bf16.bf16.f32 "
        "{%0,%1,%2,%3}, {%4,%5,%6,%7}, {%8,%9}, {%0,%1,%2,%3};\n"
        : "+f"(c[0]), "+f"(c[1]), "+f"(c[2]), "+f"(c[3])
        : "r"(a[0]), "r"(a[1]), "r"(a[2]), "r"(a[3]), "r"(b0), "r"(b1));
}

__device__ __forceinline__ void cp_async16(uint32_t smem_addr, const void* gptr) {
    asm volatile("cp.async.cg.shared.global [%0], [%1], 16;\n"
                 :: "r"(smem_addr), "l"(gptr));
}
#define CP_COMMIT() asm volatile("cp.async.commit_group;\n" ::: "memory")
#define CP_WAIT0()  asm volatile("cp.async.wait_group 0;\n" ::: "memory")

// ============================================================================
// K0: prep weights. grid = E*K CTAs of 128 threads; CTA handles one (e,k).
// W padded to D_PAD with zeros so K4's last chunk adds exactly 0.
// ============================================================================
__global__ void __launch_bounds__(128) k0_prep(const float* __restrict__ centroids,
                                               const float* __restrict__ means,
                                               const float* __restrict__ log_stds,
                                               const float* __restrict__ logits) {
    int e = blockIdx.x >> 6;
    int k = blockIdx.x & 63;
    int tid = threadIdx.x;
    __shared__ float red[128];

    const float* mrow = means    + (size_t)(e * K_N + k) * D_N;
    const float* lrow = log_stds + (size_t)(e * K_N + k) * D_N;

    float csum = 0.f;
    for (int d = tid; d < D_PAD; d += 128) {
        uint32_t pk = 0;
        if (d < D_N) {
            float ls = lrow[d];
            float m  = mrow[d];
            float iv = expf(-2.f * ls);
            float ac = -0.5f * iv;        // coeff of x^2
            float bc = m * iv;            // coeff of x
            csum += -0.5f * m * m * iv - ls;
            __nv_bfloat162 p = __floats2bfloat162_rn(bc, ac);  // lo=b, hi=a
            pk = *reinterpret_cast<uint32_t*>(&p);
        }
        d_Wpack[((e * D_PAD + d) << 6) + k] = pk;
    }
    red[tid] = csum;
    __syncthreads();
    for (int s = 64; s; s >>= 1) { if (tid < s) red[tid] += red[tid + s]; __syncthreads(); }
    if (tid == 0) {
        float ctot = red[0];
        const float* lg = logits + e * K_N;
        float mx = lg[0];
        for (int j = 1; j < K_N; j++) mx = fmaxf(mx, lg[j]);
        float s = 0.f;
        for (int j = 0; j < K_N; j++) s += expf(lg[j] - mx);
        float lse = mx + logf(s);
        d_ccomb[e * K_N + k] = ctot - 0.5f * (float)D_N * LOG_2PI + lg[k] - lse;
    }
    __syncthreads();

    if (k == 0) {   // centroid norms
        const float* crow = centroids + (size_t)e * D_N;
        float cn = 0.f;
        for (int d = tid; d < D_N; d += 128) { float c = crow[d]; cn += c * c; }
        red[tid] = cn;
        __syncthreads();
        for (int s = 64; s; s >>= 1) { if (tid < s) red[tid] += red[tid + s]; __syncthreads(); }
        if (tid == 0) d_cnorm[e] = red[0];
    }
    if (blockIdx.x == 0 && tid < E_N) { d_counts[tid] = 0; d_cursor[tid] = 0; }
}

// ============================================================================
// K1: routing. One warp per 8 rows (register-blocked -> centroid LDS / 8).
// argmin_e (||c_e||^2 - 2 x.c_e). Per-block histogram -> 8 global atomics.
// ============================================================================
#define RPW 8
__global__ void __launch_bounds__(256) k1_route(const float* __restrict__ x,
                                                const float* __restrict__ centroids) {
    __shared__ float4 cent[E_N * F4_PER_ROW];   // 25088 B
    __shared__ int hist[E_N];
    int tid = threadIdx.x;
    if (tid < E_N) hist[tid] = 0;
    const float4* c4 = reinterpret_cast<const float4*>(centroids);
    for (int j = tid; j < E_N * F4_PER_ROW; j += 256) cent[j] = c4[j];
    __syncthreads();

    int warp = tid >> 5, lane = tid & 31;
    int b0 = blockIdx.x * (8 * RPW) + warp * RPW;
    const float4* x4 = reinterpret_cast<const float4*>(x) + (size_t)b0 * F4_PER_ROW;

    float dot[RPW][E_N];
#pragma unroll
    for (int r = 0; r < RPW; r++)
#pragma unroll
        for (int e = 0; e < E_N; e++) dot[r][e] = 0.f;

    for (int j = lane; j < F4_PER_ROW; j += 32) {
        float4 xv[RPW];
#pragma unroll
        for (int r = 0; r < RPW; r++) xv[r] = x4[(size_t)r * F4_PER_ROW + j];
#pragma unroll
        for (int e = 0; e < E_N; e++) {
            float4 cv = cent[e * F4_PER_ROW + j];
#pragma unroll
            for (int r = 0; r < RPW; r++)
                dot[r][e] += xv[r].x * cv.x + xv[r].y * cv.y
                           + xv[r].z * cv.z + xv[r].w * cv.w;
        }
    }
#pragma unroll
    for (int r = 0; r < RPW; r++)
#pragma unroll
        for (int e = 0; e < E_N; e++)
#pragma unroll
            for (int o = 16; o; o >>= 1)
                dot[r][e] += __shfl_xor_sync(0xffffffffu, dot[r][e], o);

    if (lane == 0) {
#pragma unroll
        for (int r = 0; r < RPW; r++) {
            float best = 3.4e38f;
            int bi = 0;
#pragma unroll
            for (int e = 0; e < E_N; e++) {
                float s = d_cnorm[e] - 2.f * dot[r][e];
                if (s < best) { best = s; bi = e; }   // first-min == argmin
            }
            d_cluster[b0 + r] = bi;
            atomicAdd(&hist[bi], 1);
        }
    }
    __syncthreads();
    if (tid < E_N && hist[tid] > 0) atomicAdd(&d_counts[tid], hist[tid]);
}

// ============================================================================
// K3: counting-sort scatter. Block-local ranks; 8 global atomics per block.
// ============================================================================
__global__ void __launch_bounds__(256) k3_scatter() {
    __shared__ int sh_cnt[E_N];
    __shared__ int sh_base[E_N];
    __shared__ int sh_off[E_N];
    int tid = threadIdx.x;
    if (tid < E_N) sh_cnt[tid] = 0;
    if (tid == 0) {
        int off = 0;
#pragma unroll
        for (int e = 0; e < E_N; e++) { sh_off[e] = off; off += d_counts[e]; }
    }
    __syncthreads();
    int b = blockIdx.x * 256 + tid;
    int e = d_cluster[b];
    int p = atomicAdd(&sh_cnt[e], 1);
    __syncthreads();
    if (tid < E_N)
        sh_base[tid] = sh_cnt[tid] ? atomicAdd(&d_cursor[tid], sh_cnt[tid]) : 0;
    __syncthreads();
    d_sortedIdx[sh_off[e] + sh_base[e] + p] = b;
}

// ============================================================================
// K4: grouped GEMM, 256 threads (8 warps), warp tile 32x32, double-buffered,
// one sync/chunk. CTA = 128 gathered rows of one expert x 64 leaves,
// 25 chunks of 32 d. Warp (mw = warp>>1, nw = warp&1) owns rows
// [mw*32,+32) x cols [nw*32,+32): acc[2][4][4] = 32 regs.
// Fragment smem traffic per chunk: A x2 + B x4 = 64 KB (was 96 KB).
// Hazards: A store vs MMA_{cb-2} (done by sync_{cb-1}); B vs MMA_{cb-1}.
// ============================================================================
__global__ void __launch_bounds__(256, 3) k4_gemm(const float* __restrict__ x,
                                                  float* __restrict__ out) {
    extern __shared__ __align__(16) unsigned char raw[];
    int*   rowIdxS = reinterpret_cast<int*>(raw + SM_IDX_OFF);
    float* ccombS  = reinterpret_cast<float*>(raw + SM_CC_OFF);
    float* Cs      = reinterpret_cast<float*>(raw);   // epilogue, aliases A bufs

    int tid = threadIdx.x;
    int t = blockIdx.x;

    // find (expert, tile) from d_counts
    int e = -1, tileIn = 0, offE = 0, nrows = 0;
    {
        int ts = 0, off = 0;
#pragma unroll
        for (int i = 0; i < E_N; i++) {
            int c = d_counts[i];
            int tiles = (c + TILE_M - 1) >> 7;
            if (e < 0 && t >= ts && t < ts + tiles) {
                e = i; tileIn = t - ts; offE = off;
                nrows = min(TILE_M, c - tileIn * TILE_M);
            }
            ts += tiles; off += c;
        }
        if (e < 0) return;
    }
    int rowbase = offE + tileIn * TILE_M;

    if (tid < TILE_M)
        rowIdxS[tid] = d_sortedIdx[rowbase + ((tid < nrows) ? tid : 0)];
    if (tid < K_N)
        ccombS[tid] = d_ccomb[e * K_N + tid];
    __syncthreads();

    const uint32_t* WbE = d_Wpack + (size_t)e * (D_PAD * K_N);
    uint32_t smem_u32 = (uint32_t)__cvta_generic_to_shared(raw);

    int warp = tid >> 5, lane = tid & 31;
    int g = lane >> 2, tig = lane & 3;
    int mw = warp >> 1, nw = warp & 1;
    int mrow0 = mw * 32, n0 = nw * 32;

    float acc[2][4][4];
#pragma unroll
    for (int mi = 0; mi < 2; mi++)
#pragma unroll
        for (int n = 0; n < 4; n++)
#pragma unroll
            for (int q = 0; q < 4; q++) acc[mi][n][q] = 0.f;

    int r = tid >> 1, half = tid & 1;          // 2 threads per A row, 16 d each
    const float* xrow = x + (size_t)rowIdxS[r] * D_N;

    uint4 sa[4];   // staged packed A (16 d per thread)

    auto stageA = [&](int cb) {
#pragma unroll
        for (int s = 0; s < 4; s++) {
            int d = cb * CHUNK_D + half * 16 + s * 4;
            if (d < D_N) {
                float4 v = *reinterpret_cast<const float4*>(xrow + d);
                sa[s].x = pack_x_x2(v.x); sa[s].y = pack_x_x2(v.y);
                sa[s].z = pack_x_x2(v.z); sa[s].w = pack_x_x2(v.w);
            } else {
                sa[s].x = sa[s].y = sa[s].z = sa[s].w = 0u;
            }
        }
    };
    auto issueB = [&](int cb, int buf) {
        uint32_t bdst = smem_u32 + SM_B_OFF + buf * B_BUF_BYTES;
        int kk = tid >> 3, n8 = (tid & 7) * 8;   // 8 u32 per thread
        const uint32_t* src = WbE + (size_t)cb * (CHUNK_D * K_N) + tid * 8;
        cp_async16(bdst + (kk * B_PITCH + n8) * 4,     src);
        cp_async16(bdst + (kk * B_PITCH + n8 + 4) * 4, src + 4);
    };

    // ---- prologue ----
    stageA(0);
    issueB(0, 0);
    CP_COMMIT();

    for (int cb = 0; cb < NCHUNK; cb++) {
        int buf = cb & 1;
        uint32_t* As = reinterpret_cast<uint32_t*>(raw + buf * A_BUF_BYTES);
        uint32_t* Bs = reinterpret_cast<uint32_t*>(raw + SM_B_OFF + buf * B_BUF_BYTES);

        // store staged A -> As[buf] (MMA_{cb-2} done by sync_{cb-1})
#pragma unroll
        for (int s = 0; s < 4; s++)
            *reinterpret_cast<uint4*>(&As[r * A_PITCH + half * 16 + s * 4]) = sa[s];
        CP_WAIT0();          // Bs[buf] landed
        __syncthreads();     // tiles visible; MMA_{cb-1} finished everywhere

        if (cb + 1 < NCHUNK) {
            stageA(cb + 1);
            issueB(cb + 1, buf ^ 1);   // safe: MMA_{cb-1} done by this sync
            CP_COMMIT();
        }

        // ---- MMA: 32 rows x 32 cols, 4 k16 steps ----
#pragma unroll
        for (int ks = 0; ks < KSTEPS; ks++) {
            int kkb = ks * 8;
            uint32_t a[2][4];
#pragma unroll
            for (int mi = 0; mi < 2; mi++) {
                int rb = mrow0 + mi * 16;
                a[mi][0] = As[(rb + g)     * A_PITCH + kkb + tig];
                a[mi][1] = As[(rb + 8 + g) * A_PITCH + kkb + tig];
                a[mi][2] = As[(rb + g)     * A_PITCH + kkb + tig + 4];
                a[mi][3] = As[(rb + 8 + g) * A_PITCH + kkb + tig + 4];
            }
#pragma unroll
            for (int nt = 0; nt < 4; nt++) {
                uint32_t b0 = Bs[(kkb + tig)     * B_PITCH + n0 + nt * 8 + g];
                uint32_t b1 = Bs[(kkb + tig + 4) * B_PITCH + n0 + nt * 8 + g];
#pragma unroll
                for (int mi = 0; mi < 2; mi++)
                    mma_bf16(acc[mi][nt], a[mi], b0, b1);
            }
        }
    }
    __syncthreads();   // all MMAs done before Cs aliases the A buffers

    // ---- epilogue: accums -> smem ----
#pragma unroll
    for (int mi = 0; mi < 2; mi++) {
        int row0 = mrow0 + mi * 16 + g;
#pragma unroll
        for (int nt = 0; nt < 4; nt++) {
            int col = n0 + nt * 8 + tig * 2;
            Cs[row0 * C_PITCH + col]           = acc[mi][nt][0];
            Cs[row0 * C_PITCH + col + 1]       = acc[mi][nt][1];
            Cs[(row0 + 8) * C_PITCH + col]     = acc[mi][nt][2];
            Cs[(row0 + 8) * C_PITCH + col + 1] = acc[mi][nt][3];
        }
    }
    __syncthreads();

    // ---- logsumexp per row, scatter to original index ----
    if (tid < TILE_M) {
        const float* crow = &Cs[tid * C_PITCH];
        float mx = -3.4e38f;
#pragma unroll 8
        for (int j = 0; j < K_N; j++) mx = fmaxf(mx, crow[j] + ccombS[j]);
        float s = 0.f;
#pragma unroll 8
        for (int j = 0; j < K_N; j++) s += expf(crow[j] + ccombS[j] - mx);
        float ll = mx + logf(s);
        if (tid < nrows) out[rowIdxS[tid]] = ll;
    }
}

// ============================================================================
extern "C" void kernel_launch(void* const* d_in, const int* in_sizes, int n_in,
                              void* d_out, int out_size) {
    const float* x         = (const float*)d_in[0];
    const float* centroids = (const float*)d_in[1];
    const float* means     = (const float*)d_in[2];
    const float* log_stds  = (const float*)d_in[3];
    const float* logits    = (const float*)d_in[4];
    float* out = (float*)d_out;

    static bool attr_set = false;
    if (!attr_set) {
        cudaFuncSetAttribute(k4_gemm, cudaFuncAttributeMaxDynamicSharedMemorySize,
                             SM_TOTAL_K4);
        attr_set = true;
    }

    k0_prep   <<<E_N * K_N, 128>>>(centroids, means, log_stds, logits);
    k1_route  <<<B_N / (8 * RPW), 256>>>(x, centroids);
    k3_scatter<<<B_N / 256, 256>>>();
    k4_gemm   <<<B_N / TILE_M + E_N, 256, SM_TOTAL_K4>>>(x, out);
}

// round 9
// speedup vs baseline: 1.0961x; 1.0961x over previous
#include <cuda_runtime.h>
#include <cuda_bf16.h>
#include <cstdint>

// ============================================================================
// EinetMixture: route each row to nearest centroid (E=8), then compute only
// that expert's Gaussian-leaf log-likelihood (K=64 leaves) + logsumexp.
//
// leaf_ll[b,k] = sum_d ( a[e,k,d]*x^2 + b[e,k,d]*x ) + c[e,k]
// d-reduction = bf16 mma.sync GEMM; K-dim interleaved as (x[d], x^2[d]) pairs
// matching W pairs (bcoef, acoef). A is staged in smem as RAW f32 x via
// cp.async; the x^2 + bf16x2 pack happens at fragment-load time.
//
// Launches: k0 prep -> k1 route -> k3 scatter -> k4 grouped GEMM.
// ============================================================================

#define B_N 32768
#define D_N 784
#define D_PAD 800             // 25 chunks of 32 d (pad coeffs are zero)
#define E_N 8
#define K_N 64
#define F4_PER_ROW 196        // 784/4
#define X_ROW_BYTES 3136      // 784*4

#define TILE_M 128
#define CHUNK_D 32            // d's per K4 chunk (64 bf16 of K)
#define NCHUNK 25
#define KSTEPS 4              // k16 steps per chunk
#define A_PITCH 36            // u32/f32 pitch; frag banks (4g+tig) distinct
#define B_PITCH 72            // u32 pitch; frag banks (8tig+g) distinct
#define C_PITCH 66            // float pitch for epilogue

#define A_BUF_BYTES (TILE_M * A_PITCH * 4)      // 18432
#define B_BUF_BYTES (CHUNK_D * B_PITCH * 4)     // 9216
#define SM_B_OFF   (2 * A_BUF_BYTES)            // 36864
#define SM_IDX_OFF (SM_B_OFF + 2 * B_BUF_BYTES) // 55296
#define SM_CC_OFF  (SM_IDX_OFF + TILE_M * 4)    // 55808
#define SM_TOTAL_K4 (SM_CC_OFF + K_N * 4)       // 56064

#define LOG_2PI 1.8378770664093453f

// ---------------- device scratch (no allocation allowed) ----------------
__device__ __align__(16) uint32_t d_Wpack[E_N * D_PAD * K_N]; // [e][d][k] bf16x2 (b,a)
__device__ float    d_ccomb[E_N * K_N];         // c + log_softmax(logits)
__device__ float    d_cnorm[E_N];
__device__ int      d_cluster[B_N];
__device__ int      d_counts[E_N];
__device__ int      d_cursor[E_N];
__device__ int      d_sortedIdx[B_N];

// ---------------- helpers ----------------
__device__ __forceinline__ uint32_t pack_x_x2(float v) {
    __nv_bfloat162 p = __floats2bfloat162_rn(v, v * v);   // lo = x, hi = x^2
    return *reinterpret_cast<uint32_t*>(&p);
}

__device__ __forceinline__ void mma_bf16(float* c, const uint32_t* a,
                                         uint32_t b0, uint32_t b1) {
    asm volatile(
        "mma.sync.aligned.m16n8k16.row.col.f32.bf16.bf16.f32 "
        "{%0,%1,%2,%3}, {%4,%5,%6,%7}, {%8,%9}, {%0,%1,%2,%3};\n"
        : "+f"(c[0]), "+f"(c[1]), "+f"(c[2]), "+f"(c[3])
        : "r"(a[0]), "r"(a[1]), "r"(a[2]), "r"(a[3]), "r"(b0), "r"(b1));
}

__device__ __forceinline__ void cp_async16(uint32_t smem_addr, const void* gptr) {
    asm volatile("cp.async.cg.shared.global [%0], [%1], 16;\n"
                 :: "r"(smem_addr), "l"(gptr));
}
#define CP_COMMIT() asm volatile("cp.async.commit_group;\n" ::: "memory")
#define CP_WAIT0()  asm volatile("cp.async.wait_group 0;\n" ::: "memory")

// ============================================================================
// K0: prep weights. grid = E*K CTAs of 128 threads; CTA handles one (e,k).
// W padded to D_PAD with zeros so K4's last chunk adds exactly 0.
// ============================================================================
__global__ void __launch_bounds__(128) k0_prep(const float* __restrict__ centroids,
                                               const float* __restrict__ means,
                                               const float* __restrict__ log_stds,
                                               const float* __restrict__ logits) {
    int e = blockIdx.x >> 6;
    int k = blockIdx.x & 63;
    int tid = threadIdx.x;
    __shared__ float red[128];

    const float* mrow = means    + (size_t)(e * K_N + k) * D_N;
    const float* lrow = log_stds + (size_t)(e * K_N + k) * D_N;

    float csum = 0.f;
    for (int d = tid; d < D_PAD; d += 128) {
        uint32_t pk = 0;
        if (d < D_N) {
            float ls = lrow[d];
            float m  = mrow[d];
            float iv = expf(-2.f * ls);
            float ac = -0.5f * iv;        // coeff of x^2
            float bc = m * iv;            // coeff of x
            csum += -0.5f * m * m * iv - ls;
            __nv_bfloat162 p = __floats2bfloat162_rn(bc, ac);  // lo=b, hi=a
            pk = *reinterpret_cast<uint32_t*>(&p);
        }
        d_Wpack[((e * D_PAD + d) << 6) + k] = pk;
    }
    red[tid] = csum;
    __syncthreads();
    for (int s = 64; s; s >>= 1) { if (tid < s) red[tid] += red[tid + s]; __syncthreads(); }
    if (tid == 0) {
        float ctot = red[0];
        const float* lg = logits + e * K_N;
        float mx = lg[0];
        for (int j = 1; j < K_N; j++) mx = fmaxf(mx, lg[j]);
        float s = 0.f;
        for (int j = 0; j < K_N; j++) s += expf(lg[j] - mx);
        float lse = mx + logf(s);
        d_ccomb[e * K_N + k] = ctot - 0.5f * (float)D_N * LOG_2PI + lg[k] - lse;
    }
    __syncthreads();

    if (k == 0) {   // centroid norms
        const float* crow = centroids + (size_t)e * D_N;
        float cn = 0.f;
        for (int d = tid; d < D_N; d += 128) { float c = crow[d]; cn += c * c; }
        red[tid] = cn;
        __syncthreads();
        for (int s = 64; s; s >>= 1) { if (tid < s) red[tid] += red[tid + s]; __syncthreads(); }
        if (tid == 0) d_cnorm[e] = red[0];
    }
    if (blockIdx.x == 0 && tid < E_N) { d_counts[tid] = 0; d_cursor[tid] = 0; }
}

// ============================================================================
// K1: routing. One warp per 8 rows (register-blocked); centroids in smem.
// argmin_e (||c_e||^2 - 2 x.c_e). Per-block histogram -> 8 global atomics.
// ============================================================================
#define RPW 8
__global__ void __launch_bounds__(256) k1_route(const float* __restrict__ x,
                                                const float* __restrict__ centroids) {
    __shared__ float4 cent[E_N * F4_PER_ROW];   // 25088 B
    __shared__ int hist[E_N];
    int tid = threadIdx.x;
    if (tid < E_N) hist[tid] = 0;
    const float4* c4 = reinterpret_cast<const float4*>(centroids);
    for (int j = tid; j < E_N * F4_PER_ROW; j += 256) cent[j] = c4[j];
    __syncthreads();

    int warp = tid >> 5, lane = tid & 31;
    int b0 = blockIdx.x * (8 * RPW) + warp * RPW;
    const float4* x4 = reinterpret_cast<const float4*>(x) + (size_t)b0 * F4_PER_ROW;

    float dot[RPW][E_N];
#pragma unroll
    for (int r = 0; r < RPW; r++)
#pragma unroll
        for (int e = 0; e < E_N; e++) dot[r][e] = 0.f;

    for (int j = lane; j < F4_PER_ROW; j += 32) {
        float4 xv[RPW];
#pragma unroll
        for (int r = 0; r < RPW; r++) xv[r] = x4[(size_t)r * F4_PER_ROW + j];
#pragma unroll
        for (int e = 0; e < E_N; e++) {
            float4 cv = cent[e * F4_PER_ROW + j];
#pragma unroll
            for (int r = 0; r < RPW; r++)
                dot[r][e] += xv[r].x * cv.x + xv[r].y * cv.y
                           + xv[r].z * cv.z + xv[r].w * cv.w;
        }
    }
#pragma unroll
    for (int r = 0; r < RPW; r++)
#pragma unroll
        for (int e = 0; e < E_N; e++)
#pragma unroll
            for (int o = 16; o; o >>= 1)
                dot[r][e] += __shfl_xor_sync(0xffffffffu, dot[r][e], o);

    if (lane == 0) {
#pragma unroll
        for (int r = 0; r < RPW; r++) {
            float best = 3.4e38f;
            int bi = 0;
#pragma unroll
            for (int e = 0; e < E_N; e++) {
                float s = d_cnorm[e] - 2.f * dot[r][e];
                if (s < best) { best = s; bi = e; }   // first-min == argmin
            }
            d_cluster[b0 + r] = bi;
            atomicAdd(&hist[bi], 1);
        }
    }
    __syncthreads();
    if (tid < E_N && hist[tid] > 0) atomicAdd(&d_counts[tid], hist[tid]);
}

// ============================================================================
// K3: counting-sort scatter. Block-local ranks; 8 global atomics per block.
// ============================================================================
__global__ void __launch_bounds__(256) k3_scatter() {
    __shared__ int sh_cnt[E_N];
    __shared__ int sh_base[E_N];
    __shared__ int sh_off[E_N];
    int tid = threadIdx.x;
    if (tid < E_N) sh_cnt[tid] = 0;
    if (tid == 0) {
        int off = 0;
#pragma unroll
        for (int e = 0; e < E_N; e++) { sh_off[e] = off; off += d_counts[e]; }
    }
    __syncthreads();
    int b = blockIdx.x * 256 + tid;
    int e = d_cluster[b];
    int p = atomicAdd(&sh_cnt[e], 1);
    __syncthreads();
    if (tid < E_N)
        sh_base[tid] = sh_cnt[tid] ? atomicAdd(&d_cursor[tid], sh_cnt[tid]) : 0;
    __syncthreads();
    d_sortedIdx[sh_off[e] + sh_base[e] + p] = b;
}

// ============================================================================
// K4: grouped GEMM, 512 threads (16 warps), warp tile 16x32 (8m x 2n),
// double-buffered, one sync/chunk. A staged in smem as RAW f32 x via
// cp.async.cg (no LDG->reg->STS roundtrip); pack (x, x^2)->bf16x2 happens at
// fragment-load (1 LDS + 1 FMUL + 1 CVT per frag).
// Last chunk's OOB cp.asyncs are predicated off; stale smem there is finite
// f32 data multiplied by exactly-zero padded W coefficients.
// ============================================================================
__global__ void __launch_bounds__(512, 2) k4_gemm(const float* __restrict__ x,
                                                  float* __restrict__ out) {
    extern __shared__ __align__(16) unsigned char raw[];
    int*   rowIdxS = reinterpret_cast<int*>(raw + SM_IDX_OFF);
    float* ccombS  = reinterpret_cast<float*>(raw + SM_CC_OFF);
    float* Cs      = reinterpret_cast<float*>(raw);   // epilogue, aliases A bufs

    int tid = threadIdx.x;
    int t = blockIdx.x;

    // find (expert, tile) from d_counts
    int e = -1, tileIn = 0, offE = 0, nrows = 0;
    {
        int ts = 0, off = 0;
#pragma unroll
        for (int i = 0; i < E_N; i++) {
            int c = d_counts[i];
            int tiles = (c + TILE_M - 1) >> 7;
            if (e < 0 && t >= ts && t < ts + tiles) {
                e = i; tileIn = t - ts; offE = off;
                nrows = min(TILE_M, c - tileIn * TILE_M);
            }
            ts += tiles; off += c;
        }
        if (e < 0) return;
    }
    int rowbase = offE + tileIn * TILE_M;

    if (tid < TILE_M)
        rowIdxS[tid] = d_sortedIdx[rowbase + ((tid < nrows) ? tid : 0)];
    if (tid < K_N)
        ccombS[tid] = d_ccomb[e * K_N + tid];
    __syncthreads();

    const uint32_t* WbE = d_Wpack + (size_t)e * (D_PAD * K_N);
    uint32_t smem_u32 = (uint32_t)__cvta_generic_to_shared(raw);

    int warp = tid >> 5, lane = tid & 31;
    int g = lane >> 2, tig = lane & 3;
    int mw = warp >> 1, nw = warp & 1;
    int mrow0 = mw * 16, n0 = nw * 32;

    float acc[4][4];
#pragma unroll
    for (int n = 0; n < 4; n++)
#pragma unroll
        for (int q = 0; q < 4; q++) acc[n][q] = 0.f;

    // A producer mapping: 4 threads per row, 2 x 16B each (128 B/row/chunk)
    int arow = tid >> 2, aseg = tid & 3;
    const char* xrowA = reinterpret_cast<const char*>(x)
                      + (size_t)rowIdxS[arow] * X_ROW_BYTES;

    auto issueA = [&](int cb, int buf) {
        uint32_t adst = smem_u32 + buf * A_BUF_BYTES + arow * (A_PITCH * 4);
        int base = cb * 128;
#pragma unroll
        for (int p = 0; p < 2; p++) {
            int off = aseg * 16 + p * 64;
            if (base + off < X_ROW_BYTES)                 // only clips on cb=24
                cp_async16(adst + off, xrowA + base + off);
        }
    };
    auto issueB = [&](int cb, int buf) {
        uint32_t bdst = smem_u32 + SM_B_OFF + buf * B_BUF_BYTES;
        int kk = tid >> 4, n4 = (tid & 15) * 4;
        cp_async16(bdst + (kk * B_PITCH + n4) * 4,
                   WbE + (size_t)cb * (CHUNK_D * K_N) + tid * 4);
    };

    // ---- prologue ----
    issueA(0, 0);
    issueB(0, 0);
    CP_COMMIT();

    for (int cb = 0; cb < NCHUNK; cb++) {
        int buf = cb & 1;
        const float*    Af = reinterpret_cast<const float*>(raw + buf * A_BUF_BYTES);
        const uint32_t* Bs = reinterpret_cast<const uint32_t*>(raw + SM_B_OFF + buf * B_BUF_BYTES);

        CP_WAIT0();          // chunk cb's A+B landed
        __syncthreads();     // visible to all; MMA_{cb-1} finished everywhere

        if (cb + 1 < NCHUNK) {
            issueA(cb + 1, buf ^ 1);   // safe: MMA_{cb-1} done by this sync
            issueB(cb + 1, buf ^ 1);
            CP_COMMIT();
        }

        // ---- MMA: 16 rows x 32 cols, 4 k16 steps; pack A frags on the fly ----
#pragma unroll
        for (int ks = 0; ks < KSTEPS; ks++) {
            int kkb = ks * 8;
            uint32_t a[4];
            a[0] = pack_x_x2(Af[(mrow0 + g)     * A_PITCH + kkb + tig]);
            a[1] = pack_x_x2(Af[(mrow0 + 8 + g) * A_PITCH + kkb + tig]);
            a[2] = pack_x_x2(Af[(mrow0 + g)     * A_PITCH + kkb + tig + 4]);
            a[3] = pack_x_x2(Af[(mrow0 + 8 + g) * A_PITCH + kkb + tig + 4]);
#pragma unroll
            for (int nt = 0; nt < 4; nt++) {
                uint32_t b0 = Bs[(kkb + tig)     * B_PITCH + n0 + nt * 8 + g];
                uint32_t b1 = Bs[(kkb + tig + 4) * B_PITCH + n0 + nt * 8 + g];
                mma_bf16(acc[nt], a, b0, b1);
            }
        }
    }
    __syncthreads();   // all MMAs done before Cs aliases the A buffers

    // ---- epilogue: accums -> smem ----
    {
        int row0 = mrow0 + g;
#pragma unroll
        for (int nt = 0; nt < 4; nt++) {
            int col = n0 + nt * 8 + tig * 2;
            Cs[row0 * C_PITCH + col]           = acc[nt][0];
            Cs[row0 * C_PITCH + col + 1]       = acc[nt][1];
            Cs[(row0 + 8) * C_PITCH + col]     = acc[nt][2];
            Cs[(row0 + 8) * C_PITCH + col + 1] = acc[nt][3];
        }
    }
    __syncthreads();

    // ---- logsumexp per row, scatter to original index ----
    if (tid < TILE_M) {
        const float* crow = &Cs[tid * C_PITCH];
        float mx = -3.4e38f;
#pragma unroll 8
        for (int j = 0; j < K_N; j++) mx = fmaxf(mx, crow[j] + ccombS[j]);
        float s = 0.f;
#pragma unroll 8
        for (int j = 0; j < K_N; j++) s += expf(crow[j] + ccombS[j] - mx);
        float ll = mx + logf(s);
        if (tid < nrows) out[rowIdxS[tid]] = ll;
    }
}

// ============================================================================
extern "C" void kernel_launch(void* const* d_in, const int* in_sizes, int n_in,
                              void* d_out, int out_size) {
    const float* x         = (const float*)d_in[0];
    const float* centroids = (const float*)d_in[1];
    const float* means     = (const float*)d_in[2];
    const float* log_stds  = (const float*)d_in[3];
    const float* logits    = (const float*)d_in[4];
    float* out = (float*)d_out;

    static bool attr_set = false;
    if (!attr_set) {
        cudaFuncSetAttribute(k4_gemm, cudaFuncAttributeMaxDynamicSharedMemorySize,
                             SM_TOTAL_K4);
        attr_set = true;
    }

    k0_prep   <<<E_N * K_N, 128>>>(centroids, means, log_stds, logits);
    k1_route  <<<B_N / (8 * RPW), 256>>>(x, centroids);
    k3_scatter<<<B_N / 256, 256>>>();
    k4_gemm   <<<B_N / TILE_M + E_N, 512, SM_TOTAL_K4>>>(x, out);
}

// round 11
// speedup vs baseline: 1.1708x; 1.0682x over previous
#include <cuda_runtime.h>
#include <cuda_bf16.h>
#include <cstdint>

// ============================================================================
// EinetMixture: route each row to nearest centroid (E=8), then compute only
// that expert's Gaussian-leaf log-likelihood (K=64 leaves) + logsumexp.
//
// leaf_ll[b,k] = sum_d ( a[e,k,d]*x^2 + b[e,k,d]*x ) + c[e,k]
// d-reduction = bf16 mma.sync GEMM; K-dim interleaved as (x[d], x^2[d]) pairs
// matching W pairs (bcoef, acoef). A staged in smem as RAW f32 x (cp.async);
// pack (x,x^2)->bf16x2 at fragment-load time.
//
// Launches: k0 prep -> k1 route+scatter -> k4 grouped GEMM (3 total).
// ============================================================================

#define B_N 32768
#define D_N 784
#define D_PAD 800             // 25 chunks of 32 d (pad coeffs are zero)
#define E_N 8
#define K_N 64
#define F4_PER_ROW 196        // 784/4
#define X_ROW_BYTES 3136      // 784*4

#define TILE_M 128
#define CHUNK_D 32            // d's per K4 chunk (64 bf16 of K)
#define NCHUNK 25
#define KSTEPS 4              // k16 steps per chunk
#define NSTAGE 3
#define A_PITCH 36            // f32 pitch; frag banks (4g+tig) distinct
#define B_PITCH 72            // u32 pitch; frag banks (8tig+g) distinct
#define C_PITCH 66            // float pitch for epilogue

#define A_BUF_BYTES (TILE_M * A_PITCH * 4)        // 18432
#define B_BUF_BYTES (CHUNK_D * B_PITCH * 4)       // 9216
#define SM_B_OFF   (NSTAGE * A_BUF_BYTES)         // 55296
#define SM_IDX_OFF (SM_B_OFF + NSTAGE * B_BUF_BYTES)  // 82944
#define SM_CC_OFF  (SM_IDX_OFF + TILE_M * 4)      // 83456
#define SM_TOTAL_K4 (SM_CC_OFF + K_N * 4)         // 83712

#define LOG_2PI 1.8378770664093453f

// ---------------- device scratch (no allocation allowed) ----------------
__device__ __align__(16) uint32_t d_Wpack[E_N * D_PAD * K_N]; // [e][d][k] bf16x2 (b,a)
__device__ float    d_ccomb[E_N * K_N];         // c + log_softmax(logits)
__device__ int      d_cursor[E_N];              // per-expert cursor == final counts
__device__ int      d_expertList[E_N * B_N];    // row indices grouped by expert

// ---------------- helpers ----------------
__device__ __forceinline__ uint32_t pack_x_x2(float v) {
    __nv_bfloat162 p = __floats2bfloat162_rn(v, v * v);   // lo = x, hi = x^2
    return *reinterpret_cast<uint32_t*>(&p);
}

__device__ __forceinline__ void mma_bf16(float* c, const uint32_t* a,
                                         uint32_t b0, uint32_t b1) {
    asm volatile(
        "mma.sync.aligned.m16n8k16.row.col.f32.bf16.bf16.f32 "
        "{%0,%1,%2,%3}, {%4,%5,%6,%7}, {%8,%9}, {%0,%1,%2,%3};\n"
        : "+f"(c[0]), "+f"(c[1]), "+f"(c[2]), "+f"(c[3])
        : "r"(a[0]), "r"(a[1]), "r"(a[2]), "r"(a[3]), "r"(b0), "r"(b1));
}

__device__ __forceinline__ void cp_async16(uint32_t smem_addr, const void* gptr) {
    asm volatile("cp.async.cg.shared.global [%0], [%1], 16;\n"
                 :: "r"(smem_addr), "l"(gptr));
}
#define CP_COMMIT() asm volatile("cp.async.commit_group;\n" ::: "memory")
#define CP_WAIT0()  asm volatile("cp.async.wait_group 0;\n" ::: "memory")
#define CP_WAIT1()  asm volatile("cp.async.wait_group 1;\n" ::: "memory")

// ============================================================================
// K0: prep weights. grid = E*K CTAs of 128 threads; CTA handles one (e,k).
// W padded to D_PAD with zeros so K4's last chunk adds exactly 0.
// ============================================================================
__global__ void __launch_bounds__(128) k0_prep(const float* __restrict__ means,
                                               const float* __restrict__ log_stds,
                                               const float* __restrict__ logits) {
    int e = blockIdx.x >> 6;
    int k = blockIdx.x & 63;
    int tid = threadIdx.x;
    __shared__ float red[128];

    const float* mrow = means    + (size_t)(e * K_N + k) * D_N;
    const float* lrow = log_stds + (size_t)(e * K_N + k) * D_N;

    float csum = 0.f;
    for (int d = tid; d < D_PAD; d += 128) {
        uint32_t pk = 0;
        if (d < D_N) {
            float ls = lrow[d];
            float m  = mrow[d];
            float iv = __expf(-2.f * ls);
            float ac = -0.5f * iv;        // coeff of x^2
            float bc = m * iv;            // coeff of x
            csum += -0.5f * m * m * iv - ls;
            __nv_bfloat162 p = __floats2bfloat162_rn(bc, ac);  // lo=b, hi=a
            pk = *reinterpret_cast<uint32_t*>(&p);
        }
        d_Wpack[((e * D_PAD + d) << 6) + k] = pk;
    }
    red[tid] = csum;
    __syncthreads();
    for (int s = 64; s; s >>= 1) { if (tid < s) red[tid] += red[tid + s]; __syncthreads(); }
    if (tid == 0) {
        float ctot = red[0];
        const float* lg = logits + e * K_N;
        float mx = lg[0];
        for (int j = 1; j < K_N; j++) mx = fmaxf(mx, lg[j]);
        float s = 0.f;
        for (int j = 0; j < K_N; j++) s += __expf(lg[j] - mx);
        float lse = mx + logf(s);
        d_ccomb[e * K_N + k] = ctot - 0.5f * (float)D_N * LOG_2PI + lg[k] - lse;
    }
    // zero per-replay cursors (K0 runs first every replay)
    if (blockIdx.x == 0 && tid < E_N) d_cursor[tid] = 0;
}

// ============================================================================
// K1: routing + scatter fused. One warp per 8 rows; centroids + norms from
// smem (no dependency on K0's weights). Per-block histogram ranks, one
// global atomic per (block, expert), direct write into per-expert lists.
// ============================================================================
#define RPW 8
__global__ void __launch_bounds__(256) k1_route(const float* __restrict__ x,
                                                const float* __restrict__ centroids) {
    __shared__ float4 cent[E_N * F4_PER_ROW];   // 25088 B
    __shared__ float  cnormS[E_N];
    __shared__ int hist[E_N];
    __shared__ int base[E_N];
    int tid = threadIdx.x;
    int warp = tid >> 5, lane = tid & 31;
    if (tid < E_N) hist[tid] = 0;
    const float4* c4 = reinterpret_cast<const float4*>(centroids);
    for (int j = tid; j < E_N * F4_PER_ROW; j += 256) cent[j] = c4[j];
    __syncthreads();

    // centroid norms: warp w handles expert w (8 warps exactly)
    {
        float cn = 0.f;
        for (int j = lane; j < F4_PER_ROW; j += 32) {
            float4 cv = cent[warp * F4_PER_ROW + j];
            cn += cv.x * cv.x + cv.y * cv.y + cv.z * cv.z + cv.w * cv.w;
        }
#pragma unroll
        for (int o = 16; o; o >>= 1) cn += __shfl_xor_sync(0xffffffffu, cn, o);
        if (lane == 0) cnormS[warp] = cn;
    }
    __syncthreads();

    int b0 = blockIdx.x * (8 * RPW) + warp * RPW;
    const float4* x4 = reinterpret_cast<const float4*>(x) + (size_t)b0 * F4_PER_ROW;

    float dot[RPW][E_N];
#pragma unroll
    for (int r = 0; r < RPW; r++)
#pragma unroll
        for (int e = 0; e < E_N; e++) dot[r][e] = 0.f;

    for (int j = lane; j < F4_PER_ROW; j += 32) {
        float4 xv[RPW];
#pragma unroll
        for (int r = 0; r < RPW; r++) xv[r] = x4[(size_t)r * F4_PER_ROW + j];
#pragma unroll
        for (int e = 0; e < E_N; e++) {
            float4 cv = cent[e * F4_PER_ROW + j];
#pragma unroll
            for (int r = 0; r < RPW; r++)
                dot[r][e] += xv[r].x * cv.x + xv[r].y * cv.y
                           + xv[r].z * cv.z + xv[r].w * cv.w;
        }
    }
#pragma unroll
    for (int r = 0; r < RPW; r++)
#pragma unroll
        for (int e = 0; e < E_N; e++)
#pragma unroll
            for (int o = 16; o; o >>= 1)
                dot[r][e] += __shfl_xor_sync(0xffffffffu, dot[r][e], o);

    int bi[RPW], rk[RPW];
    if (lane == 0) {
#pragma unroll
        for (int r = 0; r < RPW; r++) {
            float best = 3.4e38f;
            int sel = 0;
#pragma unroll
            for (int e = 0; e < E_N; e++) {
                float s = cnormS[e] - 2.f * dot[r][e];
                if (s < best) { best = s; sel = e; }   // first-min == argmin
            }
            bi[r] = sel;
            rk[r] = atomicAdd(&hist[sel], 1);          // block-local rank
        }
    }
    __syncthreads();
    if (tid < E_N)
        base[tid] = hist[tid] ? atomicAdd(&d_cursor[tid], hist[tid]) : 0;
    __syncthreads();
    if (lane == 0) {
#pragma unroll
        for (int r = 0; r < RPW; r++)
            d_expertList[bi[r] * B_N + base[bi[r]] + rk[r]] = b0 + r;
    }
}

// ============================================================================
// K4: grouped GEMM, 512 threads (16 warps), warp tile 16x32 (8m x 2n),
// 3-stage cp.async pipeline (wait_group 1 steady-state), one sync/chunk.
// A staged as RAW f32 x; pack (x,x^2)->bf16x2 at fragment-load.
// Hazard: writing buf (cb+2)%3 races only MMA_{cb-1} (same buffer), finished
// by sync_cb. Last chunk's OOB cp.asyncs predicated off; stale smem there is
// finite f32 multiplied by exactly-zero padded W coefficients.
// ============================================================================
__global__ void __launch_bounds__(512, 2) k4_gemm(const float* __restrict__ x,
                                                  float* __restrict__ out) {
    extern __shared__ __align__(16) unsigned char raw[];
    int*   rowIdxS = reinterpret_cast<int*>(raw + SM_IDX_OFF);
    float* ccombS  = reinterpret_cast<float*>(raw + SM_CC_OFF);
    float* Cs      = reinterpret_cast<float*>(raw);   // epilogue, aliases A bufs

    int tid = threadIdx.x;
    int t = blockIdx.x;

    // find (expert, tile) from d_cursor (== per-expert counts after K1)
    int e = -1, tileIn = 0, nrows = 0;
    {
        int ts = 0;
#pragma unroll
        for (int i = 0; i < E_N; i++) {
            int c = d_cursor[i];
            int tiles = (c + TILE_M - 1) >> 7;
            if (e < 0 && t >= ts && t < ts + tiles) {
                e = i; tileIn = t - ts;
                nrows = min(TILE_M, c - tileIn * TILE_M);
            }
            ts += tiles;
        }
        if (e < 0) return;
    }

    if (tid < TILE_M)
        rowIdxS[tid] = d_expertList[e * B_N + tileIn * TILE_M
                                    + ((tid < nrows) ? tid : 0)];
    if (tid < K_N)
        ccombS[tid] = d_ccomb[e * K_N + tid];
    __syncthreads();

    const uint32_t* WbE = d_Wpack + (size_t)e * (D_PAD * K_N);
    uint32_t smem_u32 = (uint32_t)__cvta_generic_to_shared(raw);

    int warp = tid >> 5, lane = tid & 31;
    int g = lane >> 2, tig = lane & 3;
    int mw = warp >> 1, nw = warp & 1;
    int mrow0 = mw * 16, n0 = nw * 32;

    float acc[4][4];
#pragma unroll
    for (int n = 0; n < 4; n++)
#pragma unroll
        for (int q = 0; q < 4; q++) acc[n][q] = 0.f;

    // A producer mapping: 4 threads per row, 2 x 16B each (128 B/row/chunk)
    int arow = tid >> 2, aseg = tid & 3;
    const char* xrowA = reinterpret_cast<const char*>(x)
                      + (size_t)rowIdxS[arow] * X_ROW_BYTES;

    auto issueA = [&](int cb, int buf) {
        uint32_t adst = smem_u32 + buf * A_BUF_BYTES + arow * (A_PITCH * 4);
        int base = cb * 128;
#pragma unroll
        for (int p = 0; p < 2; p++) {
            int off = aseg * 16 + p * 64;
            if (base + off < X_ROW_BYTES)                 // only clips on cb=24
                cp_async16(adst + off, xrowA + base + off);
        }
    };
    auto issueB = [&](int cb, int buf) {
        uint32_t bdst = smem_u32 + SM_B_OFF + buf * B_BUF_BYTES;
        int kk = tid >> 4, n4 = (tid & 15) * 4;
        cp_async16(bdst + (kk * B_PITCH + n4) * 4,
                   WbE + (size_t)cb * (CHUNK_D * K_N) + tid * 4);
    };

    // ---- prologue: chunks 0 and 1 ----
    issueA(0, 0); issueB(0, 0); CP_COMMIT();
    issueA(1, 1); issueB(1, 1); CP_COMMIT();

    int buf = 0;
    for (int cb = 0; cb < NCHUNK; cb++) {
        const float*    Af = reinterpret_cast<const float*>(raw + buf * A_BUF_BYTES);
        const uint32_t* Bs = reinterpret_cast<const uint32_t*>(raw + SM_B_OFF + buf * B_BUF_BYTES);

        if (cb < NCHUNK - 1) CP_WAIT1();   // chunk cb landed (one group may fly)
        else                 CP_WAIT0();   // final chunk: everything landed
        __syncthreads();                   // visible; MMA_{cb-1} finished

        if (cb + 2 < NCHUNK) {
            int nb = buf + 2; if (nb >= NSTAGE) nb -= NSTAGE;
            issueA(cb + 2, nb);            // safe: MMA_{cb-1} done by this sync
            issueB(cb + 2, nb);
            CP_COMMIT();
        }

        // ---- MMA: 16 rows x 32 cols, 4 k16 steps; pack A frags on the fly ----
#pragma unroll
        for (int ks = 0; ks < KSTEPS; ks++) {
            int kkb = ks * 8;
            uint32_t a[4];
            a[0] = pack_x_x2(Af[(mrow0 + g)     * A_PITCH + kkb + tig]);
            a[1] = pack_x_x2(Af[(mrow0 + 8 + g) * A_PITCH + kkb + tig]);
            a[2] = pack_x_x2(Af[(mrow0 + g)     * A_PITCH + kkb + tig + 4]);
            a[3] = pack_x_x2(Af[(mrow0 + 8 + g) * A_PITCH + kkb + tig + 4]);
#pragma unroll
            for (int nt = 0; nt < 4; nt++) {
                uint32_t b0 = Bs[(kkb + tig)     * B_PITCH + n0 + nt * 8 + g];
                uint32_t b1 = Bs[(kkb + tig + 4) * B_PITCH + n0 + nt * 8 + g];
                mma_bf16(acc[nt], a, b0, b1);
            }
        }
        buf++; if (buf >= NSTAGE) buf = 0;
    }
    __syncthreads();   // all MMAs done before Cs aliases the A buffers

    // ---- epilogue: accums -> smem ----
    {
        int row0 = mrow0 + g;
#pragma unroll
        for (int nt = 0; nt < 4; nt++) {
            int col = n0 + nt * 8 + tig * 2;
            Cs[row0 * C_PITCH + col]           = acc[nt][0];
            Cs[row0 * C_PITCH + col + 1]       = acc[nt][1];
            Cs[(row0 + 8) * C_PITCH + col]     = acc[nt][2];
            Cs[(row0 + 8) * C_PITCH + col + 1] = acc[nt][3];
        }
    }
    __syncthreads();

    // ---- logsumexp per row, scatter to original index ----
    if (tid < TILE_M) {
        const float* crow = &Cs[tid * C_PITCH];
        float mx = -3.4e38f;
#pragma unroll 8
        for (int j = 0; j < K_N; j++) mx = fmaxf(mx, crow[j] + ccombS[j]);
        float s = 0.f;
#pragma unroll 8
        for (int j = 0; j < K_N; j++) s += expf(crow[j] + ccombS[j] - mx);
        float ll = mx + logf(s);
        if (tid < nrows) out[rowIdxS[tid]] = ll;
    }
}

// ============================================================================
extern "C" void kernel_launch(void* const* d_in, const int* in_sizes, int n_in,
                              void* d_out, int out_size) {
    const float* x         = (const float*)d_in[0];
    const float* centroids = (const float*)d_in[1];
    const float* means     = (const float*)d_in[2];
    const float* log_stds  = (const float*)d_in[3];
    const float* logits    = (const float*)d_in[4];
    float* out = (float*)d_out;

    static bool attr_set = false;
    if (!attr_set) {
        cudaFuncSetAttribute(k4_gemm, cudaFuncAttributeMaxDynamicSharedMemorySize,
                             SM_TOTAL_K4);
        attr_set = true;
    }

    k0_prep <<<E_N * K_N, 128>>>(means, log_stds, logits);
    k1_route<<<B_N / (8 * RPW), 256>>>(x, centroids);
    k4_gemm <<<B_N / TILE_M + E_N, 512, SM_TOTAL_K4>>>(x, out);
}

// round 14
// speedup vs baseline: 1.1938x; 1.0196x over previous
#include <cuda_runtime.h>
#include <cuda_bf16.h>
#include <cstdint>

// ============================================================================
// EinetMixture: route each row to nearest centroid (E=8), then compute only
// that expert's Gaussian-leaf log-likelihood (K=64 leaves) + logsumexp.
//
// leaf_ll[b,k] = sum_d ( a[e,k,d]*x^2 + b[e,k,d]*x ) + c[e,k]
// d-reduction = bf16 mma.sync GEMM; K-dim interleaved as (x[d], x^2[d]) pairs
// matching W pairs (bcoef, acoef). A staged in smem as RAW f32 x (cp.async);
// pack (x,x^2)->bf16x2 at fragment-load time.
//
// Launches: k0 prep -> k1 route+scatter -> k4 grouped GEMM (serial; the
// stream-fork variant hard-killed the harness container twice).
// ============================================================================

#define B_N 32768
#define D_N 784
#define D_PAD 800             // 25 chunks of 32 d (pad coeffs are zero)
#define E_N 8
#define K_N 64
#define F4_PER_ROW 196        // 784/4
#define X_ROW_BYTES 3136      // 784*4

#define TILE_M 128
#define CHUNK_D 32            // d's per K4 chunk (64 bf16 of K)
#define NCHUNK 25
#define KSTEPS 4              // k16 steps per chunk
#define NSTAGE 3
#define A_PITCH 36            // f32 pitch; frag banks (4g+tig) distinct
#define B_PITCH 72            // u32 pitch; frag banks (8tig+g) distinct
#define C_PITCH 66            // float pitch for epilogue

#define A_BUF_BYTES (TILE_M * A_PITCH * 4)        // 18432
#define B_BUF_BYTES (CHUNK_D * B_PITCH * 4)       // 9216
#define SM_B_OFF   (NSTAGE * A_BUF_BYTES)         // 55296
#define SM_IDX_OFF (SM_B_OFF + NSTAGE * B_BUF_BYTES)  // 82944
#define SM_CC_OFF  (SM_IDX_OFF + TILE_M * 4)      // 83456
#define SM_TOTAL_K4 (SM_CC_OFF + K_N * 4)         // 83712

#define LOG_2PI 1.8378770664093453f

// ---------------- device scratch (no allocation allowed) ----------------
__device__ __align__(16) uint32_t d_Wpack[E_N * D_PAD * K_N]; // [e][d][k] bf16x2 (b,a)
__device__ float    d_ccomb[E_N * K_N];         // c + log_softmax(logits)
__device__ int      d_cursor[E_N];              // per-expert cursor == final counts
__device__ int      d_expertList[E_N * B_N];    // row indices grouped by expert

// ---------------- helpers ----------------
__device__ __forceinline__ uint32_t pack_x_x2(float v) {
    __nv_bfloat162 p = __floats2bfloat162_rn(v, v * v);   // lo = x, hi = x^2
    return *reinterpret_cast<uint32_t*>(&p);
}

__device__ __forceinline__ void mma_bf16(float* c, const uint32_t* a,
                                         uint32_t b0, uint32_t b1) {
    asm volatile(
        "mma.sync.aligned.m16n8k16.row.col.f32.bf16.bf16.f32 "
        "{%0,%1,%2,%3}, {%4,%5,%6,%7}, {%8,%9}, {%0,%1,%2,%3};\n"
        : "+f"(c[0]), "+f"(c[1]), "+f"(c[2]), "+f"(c[3])
        : "r"(a[0]), "r"(a[1]), "r"(a[2]), "r"(a[3]), "r"(b0), "r"(b1));
}

__device__ __forceinline__ void cp_async16(uint32_t smem_addr, const void* gptr) {
    asm volatile("cp.async.cg.shared.global [%0], [%1], 16;\n"
                 :: "r"(smem_addr), "l"(gptr));
}
#define CP_COMMIT() asm volatile("cp.async.commit_group;\n" ::: "memory")
#define CP_WAIT0()  asm volatile("cp.async.wait_group 0;\n" ::: "memory")
#define CP_WAIT1()  asm volatile("cp.async.wait_group 1;\n" ::: "memory")

// ============================================================================
// K0: prep weights. grid = E*K CTAs of 256 threads; CTA handles one (e,k).
// W padded to D_PAD with zeros so K4's last chunk adds exactly 0.
// Also zeroes the per-replay cursors (runs first every replay).
// ============================================================================
__global__ void __launch_bounds__(256) k0_prep(const float* __restrict__ means,
                                               const float* __restrict__ log_stds,
                                               const float* __restrict__ logits) {
    int e = blockIdx.x >> 6;
    int k = blockIdx.x & 63;
    int tid = threadIdx.x;
    __shared__ float red[256];

    const float* mrow = means    + (size_t)(e * K_N + k) * D_N;
    const float* lrow = log_stds + (size_t)(e * K_N + k) * D_N;

    float csum = 0.f;
#pragma unroll
    for (int it = 0; it < 4; it++) {
        int d = tid + it * 256;
        if (d >= D_PAD) break;
        uint32_t pk = 0;
        if (d < D_N) {
            float ls = lrow[d];
            float m  = mrow[d];
            float iv = __expf(-2.f * ls);
            float ac = -0.5f * iv;        // coeff of x^2
            float bc = m * iv;            // coeff of x
            csum += -0.5f * m * m * iv - ls;
            __nv_bfloat162 p = __floats2bfloat162_rn(bc, ac);  // lo=b, hi=a
            pk = *reinterpret_cast<uint32_t*>(&p);
        }
        d_Wpack[((e * D_PAD + d) << 6) + k] = pk;
    }
    red[tid] = csum;
    __syncthreads();
    for (int s = 128; s; s >>= 1) { if (tid < s) red[tid] += red[tid + s]; __syncthreads(); }
    if (tid == 0) {
        float ctot = red[0];
        const float* lg = logits + e * K_N;
        float mx = lg[0];
        for (int j = 1; j < K_N; j++) mx = fmaxf(mx, lg[j]);
        float s = 0.f;
        for (int j = 0; j < K_N; j++) s += __expf(lg[j] - mx);
        float lse = mx + logf(s);
        d_ccomb[e * K_N + k] = ctot - 0.5f * (float)D_N * LOG_2PI + lg[k] - lse;
    }
    // zero per-replay cursors
    if (blockIdx.x == 0 && tid < E_N) d_cursor[tid] = 0;
}

// ============================================================================
// K1: routing + scatter fused. One warp per 8 rows; centroids + norms from
// smem. Per-block histogram ranks, one global atomic per (block, expert),
// direct write into per-expert lists.
// ============================================================================
#define RPW 8
__global__ void __launch_bounds__(256) k1_route(const float* __restrict__ x,
                                                const float* __restrict__ centroids) {
    __shared__ float4 cent[E_N * F4_PER_ROW];   // 25088 B
    __shared__ float  cnormS[E_N];
    __shared__ int hist[E_N];
    __shared__ int base[E_N];
    int tid = threadIdx.x;
    int warp = tid >> 5, lane = tid & 31;
    if (tid < E_N) hist[tid] = 0;
    const float4* c4 = reinterpret_cast<const float4*>(centroids);
    for (int j = tid; j < E_N * F4_PER_ROW; j += 256) cent[j] = c4[j];
    __syncthreads();

    // centroid norms: warp w handles expert w (8 warps exactly)
    {
        float cn = 0.f;
        for (int j = lane; j < F4_PER_ROW; j += 32) {
            float4 cv = cent[warp * F4_PER_ROW + j];
            cn += cv.x * cv.x + cv.y * cv.y + cv.z * cv.z + cv.w * cv.w;
        }
#pragma unroll
        for (int o = 16; o; o >>= 1) cn += __shfl_xor_sync(0xffffffffu, cn, o);
        if (lane == 0) cnormS[warp] = cn;
    }
    __syncthreads();

    int b0 = blockIdx.x * (8 * RPW) + warp * RPW;
    const float4* x4 = reinterpret_cast<const float4*>(x) + (size_t)b0 * F4_PER_ROW;

    float dot[RPW][E_N];
#pragma unroll
    for (int r = 0; r < RPW; r++)
#pragma unroll
        for (int e = 0; e < E_N; e++) dot[r][e] = 0.f;

    for (int j = lane; j < F4_PER_ROW; j += 32) {
        float4 xv[RPW];
#pragma unroll
        for (int r = 0; r < RPW; r++) xv[r] = x4[(size_t)r * F4_PER_ROW + j];
#pragma unroll
        for (int e = 0; e < E_N; e++) {
            float4 cv = cent[e * F4_PER_ROW + j];
#pragma unroll
            for (int r = 0; r < RPW; r++)
                dot[r][e] += xv[r].x * cv.x + xv[r].y * cv.y
                           + xv[r].z * cv.z + xv[r].w * cv.w;
        }
    }
#pragma unroll
    for (int r = 0; r < RPW; r++)
#pragma unroll
        for (int e = 0; e < E_N; e++)
#pragma unroll
            for (int o = 16; o; o >>= 1)
                dot[r][e] += __shfl_xor_sync(0xffffffffu, dot[r][e], o);

    int bi[RPW], rk[RPW];
    if (lane == 0) {
#pragma unroll
        for (int r = 0; r < RPW; r++) {
            float best = 3.4e38f;
            int sel = 0;
#pragma unroll
            for (int e = 0; e < E_N; e++) {
                float s = cnormS[e] - 2.f * dot[r][e];
                if (s < best) { best = s; sel = e; }   // first-min == argmin
            }
            bi[r] = sel;
            rk[r] = atomicAdd(&hist[sel], 1);          // block-local rank
        }
    }
    __syncthreads();
    if (tid < E_N)
        base[tid] = hist[tid] ? atomicAdd(&d_cursor[tid], hist[tid]) : 0;
    __syncthreads();
    if (lane == 0) {
#pragma unroll
        for (int r = 0; r < RPW; r++)
            d_expertList[bi[r] * B_N + base[bi[r]] + rk[r]] = b0 + r;
    }
}

// ============================================================================
// K4: grouped GEMM, 512 threads (16 warps), warp tile 16x32 (8m x 2n),
// 3-stage cp.async pipeline (wait_group 1 steady-state), one sync/chunk.
// A staged as RAW f32 x; pack (x,x^2)->bf16x2 at fragment-load.
// ============================================================================
__global__ void __launch_bounds__(512, 2) k4_gemm(const float* __restrict__ x,
                                                  float* __restrict__ out) {
    extern __shared__ __align__(16) unsigned char raw[];
    int*   rowIdxS = reinterpret_cast<int*>(raw + SM_IDX_OFF);
    float* ccombS  = reinterpret_cast<float*>(raw + SM_CC_OFF);
    float* Cs      = reinterpret_cast<float*>(raw);   // epilogue, aliases A bufs

    int tid = threadIdx.x;
    int t = blockIdx.x;

    // find (expert, tile) from d_cursor (== per-expert counts after K1)
    int e = -1, tileIn = 0, nrows = 0;
    {
        int ts = 0;
#pragma unroll
        for (int i = 0; i < E_N; i++) {
            int c = d_cursor[i];
            int tiles = (c + TILE_M - 1) >> 7;
            if (e < 0 && t >= ts && t < ts + tiles) {
                e = i; tileIn = t - ts;
                nrows = min(TILE_M, c - tileIn * TILE_M);
            }
            ts += tiles;
        }
        if (e < 0) return;
    }

    if (tid < TILE_M)
        rowIdxS[tid] = d_expertList[e * B_N + tileIn * TILE_M
                                    + ((tid < nrows) ? tid : 0)];
    if (tid < K_N)
        ccombS[tid] = d_ccomb[e * K_N + tid];
    __syncthreads();

    const uint32_t* WbE = d_Wpack + (size_t)e * (D_PAD * K_N);
    uint32_t smem_u32 = (uint32_t)__cvta_generic_to_shared(raw);

    int warp = tid >> 5, lane = tid & 31;
    int g = lane >> 2, tig = lane & 3;
    int mw = warp >> 1, nw = warp & 1;
    int mrow0 = mw * 16, n0 = nw * 32;

    float acc[4][4];
#pragma unroll
    for (int n = 0; n < 4; n++)
#pragma unroll
        for (int q = 0; q < 4; q++) acc[n][q] = 0.f;

    // A producer mapping: 4 threads per row, 2 x 16B each (128 B/row/chunk)
    int arow = tid >> 2, aseg = tid & 3;
    const char* xrowA = reinterpret_cast<const char*>(x)
                      + (size_t)rowIdxS[arow] * X_ROW_BYTES;

    auto issueA = [&](int cb, int buf) {
        uint32_t adst = smem_u32 + buf * A_BUF_BYTES + arow * (A_PITCH * 4);
        int base = cb * 128;
#pragma unroll
        for (int p = 0; p < 2; p++) {
            int off = aseg * 16 + p * 64;
            if (base + off < X_ROW_BYTES)                 // only clips on cb=24
                cp_async16(adst + off, xrowA + base + off);
        }
    };
    auto issueB = [&](int cb, int buf) {
        uint32_t bdst = smem_u32 + SM_B_OFF + buf * B_BUF_BYTES;
        int kk = tid >> 4, n4 = (tid & 15) * 4;
        cp_async16(bdst + (kk * B_PITCH + n4) * 4,
                   WbE + (size_t)cb * (CHUNK_D * K_N) + tid * 4);
    };

    // ---- prologue: chunks 0 and 1 ----
    issueA(0, 0); issueB(0, 0); CP_COMMIT();
    issueA(1, 1); issueB(1, 1); CP_COMMIT();

    int buf = 0;
    for (int cb = 0; cb < NCHUNK; cb++) {
        const float*    Af = reinterpret_cast<const float*>(raw + buf * A_BUF_BYTES);
        const uint32_t* Bs = reinterpret_cast<const uint32_t*>(raw + SM_B_OFF + buf * B_BUF_BYTES);

        if (cb < NCHUNK - 1) CP_WAIT1();   // chunk cb landed (one group may fly)
        else                 CP_WAIT0();   // final chunk: everything landed
        __syncthreads();                   // visible; MMA_{cb-1} finished

        if (cb + 2 < NCHUNK) {
            int nb = buf + 2; if (nb >= NSTAGE) nb -= NSTAGE;
            issueA(cb + 2, nb);            // safe: MMA_{cb-1} done by this sync
            issueB(cb + 2, nb);
            CP_COMMIT();
        }

        // ---- MMA: 16 rows x 32 cols, 4 k16 steps; pack A frags on the fly ----
#pragma unroll
        for (int ks = 0; ks < KSTEPS; ks++) {
            int kkb = ks * 8;
            uint32_t a[4];
            a[0] = pack_x_x2(Af[(mrow0 + g)     * A_PITCH + kkb + tig]);
            a[1] = pack_x_x2(Af[(mrow0 + 8 + g) * A_PITCH + kkb + tig]);
            a[2] = pack_x_x2(Af[(mrow0 + g)     * A_PITCH + kkb + tig + 4]);
            a[3] = pack_x_x2(Af[(mrow0 + 8 + g) * A_PITCH + kkb + tig + 4]);
#pragma unroll
            for (int nt = 0; nt < 4; nt++) {
                uint32_t b0 = Bs[(kkb + tig)     * B_PITCH + n0 + nt * 8 + g];
                uint32_t b1 = Bs[(kkb + tig + 4) * B_PITCH + n0 + nt * 8 + g];
                mma_bf16(acc[nt], a, b0, b1);
            }
        }
        buf++; if (buf >= NSTAGE) buf = 0;
    }
    __syncthreads();   // all MMAs done before Cs aliases the A buffers

    // ---- epilogue: accums -> smem ----
    {
        int row0 = mrow0 + g;
#pragma unroll
        for (int nt = 0; nt < 4; nt++) {
            int col = n0 + nt * 8 + tig * 2;
            Cs[row0 * C_PITCH + col]           = acc[nt][0];
            Cs[row0 * C_PITCH + col + 1]       = acc[nt][1];
            Cs[(row0 + 8) * C_PITCH + col]     = acc[nt][2];
            Cs[(row0 + 8) * C_PITCH + col + 1] = acc[nt][3];
        }
    }
    __syncthreads();

    // ---- logsumexp per row, scatter to original index ----
    if (tid < TILE_M) {
        const float* crow = &Cs[tid * C_PITCH];
        float mx = -3.4e38f;
#pragma unroll 8
        for (int j = 0; j < K_N; j++) mx = fmaxf(mx, crow[j] + ccombS[j]);
        float s = 0.f;
#pragma unroll 8
        for (int j = 0; j < K_N; j++) s += expf(crow[j] + ccombS[j] - mx);
        float ll = mx + logf(s);
        if (tid < nrows) out[rowIdxS[tid]] = ll;
    }
}

// ============================================================================
extern "C" void kernel_launch(void* const* d_in, const int* in_sizes, int n_in,
                              void* d_out, int out_size) {
    const float* x         = (const float*)d_in[0];
    const float* centroids = (const float*)d_in[1];
    const float* means     = (const float*)d_in[2];
    const float* log_stds  = (const float*)d_in[3];
    const float* logits    = (const float*)d_in[4];
    float* out = (float*)d_out;

    static bool attr_set = false;
    if (!attr_set) {
        cudaFuncSetAttribute(k4_gemm, cudaFuncAttributeMaxDynamicSharedMemorySize,
                             SM_TOTAL_K4);
        attr_set = true;
    }

    k0_prep <<<E_N * K_N, 256>>>(means, log_stds, logits);
    k1_route<<<B_N / (8 * RPW), 256>>>(x, centroids);
    k4_gemm <<<B_N / TILE_M + E_N, 512, SM_TOTAL_K4>>>(x, out);
}

// round 15
// speedup vs baseline: 1.2004x; 1.0056x over previous
#include <cuda_runtime.h>
#include <cuda_bf16.h>
#include <cstdint>

// ============================================================================
// EinetMixture: route each row to nearest centroid (E=8), then compute only
// that expert's Gaussian-leaf log-likelihood (K=64 leaves) + logsumexp.
//
// leaf_ll[b,k] = sum_d ( a[e,k,d]*x^2 + b[e,k,d]*x ) + c[e,k]
// d-reduction = bf16 mma.sync GEMM; K-dim interleaved as (x[d], x^2[d]) pairs
// matching W pairs (bcoef, acoef). A staged in smem as RAW f32 x (cp.async);
// pack (x,x^2)->bf16x2 at fragment-load time.
//
// Launches: k0 prep -> k1 route+scatter -> k4 grouped GEMM (serial; stream
// fork in kernel_launch kills the harness container - do not reintroduce).
// ============================================================================

#define B_N 32768
#define D_N 784
#define D_PAD 800             // 25 chunks of 32 d (pad coeffs are zero)
#define E_N 8
#define K_N 64
#define F4_PER_ROW 196        // 784/4
#define X_ROW_BYTES 3136      // 784*4

#define TILE_M 128
#define CHUNK_D 32            // d's per K4 chunk (64 bf16 of K)
#define NCHUNK 25
#define KSTEPS 4              // k16 steps per chunk
#define NSTAGE 4
#define A_PITCH 36            // f32 pitch; frag banks (4g+tig) distinct
#define B_PITCH 72            // u32 pitch; frag banks (8tig+g) distinct
#define C_PITCH 66            // float pitch for epilogue

#define A_BUF_BYTES (TILE_M * A_PITCH * 4)        // 18432
#define B_BUF_BYTES (CHUNK_D * B_PITCH * 4)       // 9216
#define SM_B_OFF   (NSTAGE * A_BUF_BYTES)         // 73728
#define SM_IDX_OFF (SM_B_OFF + NSTAGE * B_BUF_BYTES)  // 110592
#define SM_CC_OFF  (SM_IDX_OFF + TILE_M * 4)      // 111104
#define SM_TOTAL_K4 (SM_CC_OFF + K_N * 4)         // 111360 (x2 CTAs = 222.7KB)

#define LOG_2PI 1.8378770664093453f

// ---------------- device scratch (no allocation allowed) ----------------
__device__ __align__(16) uint32_t d_Wpack[E_N * D_PAD * K_N]; // [e][d][k] bf16x2 (b,a)
__device__ float    d_ccomb[E_N * K_N];         // c + log_softmax(logits)
__device__ int      d_cursor[E_N];              // per-expert cursor == final counts
__device__ int      d_expertList[E_N * B_N];    // row indices grouped by expert

// ---------------- helpers ----------------
__device__ __forceinline__ uint32_t pack_x_x2(float v) {
    __nv_bfloat162 p = __floats2bfloat162_rn(v, v * v);   // lo = x, hi = x^2
    return *reinterpret_cast<uint32_t*>(&p);
}

__device__ __forceinline__ void mma_bf16(float* c, const uint32_t* a,
                                         uint32_t b0, uint32_t b1) {
    asm volatile(
        "mma.sync.aligned.m16n8k16.row.col.f32.bf16.bf16.f32 "
        "{%0,%1,%2,%3}, {%4,%5,%6,%7}, {%8,%9}, {%0,%1,%2,%3};\n"
        : "+f"(c[0]), "+f"(c[1]), "+f"(c[2]), "+f"(c[3])
        : "r"(a[0]), "r"(a[1]), "r"(a[2]), "r"(a[3]), "r"(b0), "r"(b1));
}

__device__ __forceinline__ void cp_async16(uint32_t smem_addr, const void* gptr) {
    asm volatile("cp.async.cg.shared.global [%0], [%1], 16;\n"
                 :: "r"(smem_addr), "l"(gptr));
}
#define CP_COMMIT() asm volatile("cp.async.commit_group;\n" ::: "memory")
#define CP_WAIT0()  asm volatile("cp.async.wait_group 0;\n" ::: "memory")
#define CP_WAIT1()  asm volatile("cp.async.wait_group 1;\n" ::: "memory")
#define CP_WAIT2()  asm volatile("cp.async.wait_group 2;\n" ::: "memory")

// ============================================================================
// K0: prep weights. grid = E*K CTAs of 256 threads; CTA handles one (e,k).
// Branchless structure: iterations 0-2 are unconditional (d<=767<784); only
// the tail (d=768..1023) is predicated. All loads front-batched for MLP.
// ============================================================================
__global__ void __launch_bounds__(256) k0_prep(const float* __restrict__ means,
                                               const float* __restrict__ log_stds,
                                               const float* __restrict__ logits) {
    int e = blockIdx.x >> 6;
    int k = blockIdx.x & 63;
    int tid = threadIdx.x;
    __shared__ float red[256];

    const float* mrow = means    + (size_t)(e * K_N + k) * D_N;
    const float* lrow = log_stds + (size_t)(e * K_N + k) * D_N;

    // ---- front-batched loads (MLP 8) ----
    float mv[3], lv[3];
#pragma unroll
    for (int it = 0; it < 3; it++) {
        int d = tid + it * 256;            // <= 767 < 784, always valid
        mv[it] = mrow[d];
        lv[it] = lrow[d];
    }
    int d3 = tid + 768;                    // 768..1023
    bool v3 = d3 < D_N;                    // data exists only below 784
    float m3 = v3 ? mrow[d3] : 0.f;
    float l3 = v3 ? lrow[d3] : 0.f;

    // ---- compute + store ----
    float csum = 0.f;
#pragma unroll
    for (int it = 0; it < 3; it++) {
        int d = tid + it * 256;
        float iv = __expf(-2.f * lv[it]);
        float bc = mv[it] * iv;
        csum += -0.5f * mv[it] * mv[it] * iv - lv[it];
        __nv_bfloat162 p = __floats2bfloat162_rn(bc, -0.5f * iv);   // lo=b, hi=a
        d_Wpack[((e * D_PAD + d) << 6) + k] = *reinterpret_cast<uint32_t*>(&p);
    }
    if (d3 < D_PAD) {                      // tail: d 768..799 (zeros past 783)
        uint32_t pk = 0;
        if (v3) {
            float iv = __expf(-2.f * l3);
            float bc = m3 * iv;
            csum += -0.5f * m3 * m3 * iv - l3;
            __nv_bfloat162 p = __floats2bfloat162_rn(bc, -0.5f * iv);
            pk = *reinterpret_cast<uint32_t*>(&p);
        }
        d_Wpack[((e * D_PAD + d3) << 6) + k] = pk;
    }

    red[tid] = csum;
    __syncthreads();
    for (int s = 128; s; s >>= 1) { if (tid < s) red[tid] += red[tid + s]; __syncthreads(); }
    if (tid == 0) {
        float ctot = red[0];
        const float* lg = logits + e * K_N;
        float mx = lg[0];
        for (int j = 1; j < K_N; j++) mx = fmaxf(mx, lg[j]);
        float s = 0.f;
        for (int j = 0; j < K_N; j++) s += __expf(lg[j] - mx);
        float lse = mx + logf(s);
        d_ccomb[e * K_N + k] = ctot - 0.5f * (float)D_N * LOG_2PI + lg[k] - lse;
    }
    // zero per-replay cursors
    if (blockIdx.x == 0 && tid < E_N) d_cursor[tid] = 0;
}

// ============================================================================
// K1: routing + scatter fused. One warp per 8 rows; centroids + norms from
// smem. Per-block histogram ranks, one global atomic per (block, expert),
// direct write into per-expert lists.
// ============================================================================
#define RPW 8
__global__ void __launch_bounds__(256) k1_route(const float* __restrict__ x,
                                                const float* __restrict__ centroids) {
    __shared__ float4 cent[E_N * F4_PER_ROW];   // 25088 B
    __shared__ float  cnormS[E_N];
    __shared__ int hist[E_N];
    __shared__ int base[E_N];
    int tid = threadIdx.x;
    int warp = tid >> 5, lane = tid & 31;
    if (tid < E_N) hist[tid] = 0;
    const float4* c4 = reinterpret_cast<const float4*>(centroids);
    for (int j = tid; j < E_N * F4_PER_ROW; j += 256) cent[j] = c4[j];
    __syncthreads();

    // centroid norms: warp w handles expert w (8 warps exactly)
    {
        float cn = 0.f;
        for (int j = lane; j < F4_PER_ROW; j += 32) {
            float4 cv = cent[warp * F4_PER_ROW + j];
            cn += cv.x * cv.x + cv.y * cv.y + cv.z * cv.z + cv.w * cv.w;
        }
#pragma unroll
        for (int o = 16; o; o >>= 1) cn += __shfl_xor_sync(0xffffffffu, cn, o);
        if (lane == 0) cnormS[warp] = cn;
    }
    __syncthreads();

    int b0 = blockIdx.x * (8 * RPW) + warp * RPW;
    const float4* x4 = reinterpret_cast<const float4*>(x) + (size_t)b0 * F4_PER_ROW;

    float dot[RPW][E_N];
#pragma unroll
    for (int r = 0; r < RPW; r++)
#pragma unroll
        for (int e = 0; e < E_N; e++) dot[r][e] = 0.f;

    for (int j = lane; j < F4_PER_ROW; j += 32) {
        float4 xv[RPW];
#pragma unroll
        for (int r = 0; r < RPW; r++) xv[r] = x4[(size_t)r * F4_PER_ROW + j];
#pragma unroll
        for (int e = 0; e < E_N; e++) {
            float4 cv = cent[e * F4_PER_ROW + j];
#pragma unroll
            for (int r = 0; r < RPW; r++)
                dot[r][e] += xv[r].x * cv.x + xv[r].y * cv.y
                           + xv[r].z * cv.z + xv[r].w * cv.w;
        }
    }
#pragma unroll
    for (int r = 0; r < RPW; r++)
#pragma unroll
        for (int e = 0; e < E_N; e++)
#pragma unroll
            for (int o = 16; o; o >>= 1)
                dot[r][e] += __shfl_xor_sync(0xffffffffu, dot[r][e], o);

    int bi[RPW], rk[RPW];
    if (lane == 0) {
#pragma unroll
        for (int r = 0; r < RPW; r++) {
            float best = 3.4e38f;
            int sel = 0;
#pragma unroll
            for (int e = 0; e < E_N; e++) {
                float s = cnormS[e] - 2.f * dot[r][e];
                if (s < best) { best = s; sel = e; }   // first-min == argmin
            }
            bi[r] = sel;
            rk[r] = atomicAdd(&hist[sel], 1);          // block-local rank
        }
    }
    __syncthreads();
    if (tid < E_N)
        base[tid] = hist[tid] ? atomicAdd(&d_cursor[tid], hist[tid]) : 0;
    __syncthreads();
    if (lane == 0) {
#pragma unroll
        for (int r = 0; r < RPW; r++)
            d_expertList[bi[r] * B_N + base[bi[r]] + rk[r]] = b0 + r;
    }
}

// ============================================================================
// K4: grouped GEMM, 512 threads (16 warps), warp tile 16x32 (8m x 2n),
// 4-stage cp.async pipeline (wait_group 2 steady-state: prefetch 3 chunks
// ahead), one sync/chunk. A staged as RAW f32 x; pack at fragment-load.
// Hazard: writing buf (cb+3)%4 == (cb-1)%4 races only MMA_{cb-1}, finished
// by sync_cb; in-flight chunks cb+1/cb+2 land in distinct buffers.
// ============================================================================
__global__ void __launch_bounds__(512, 2) k4_gemm(const float* __restrict__ x,
                                                  float* __restrict__ out) {
    extern __shared__ __align__(16) unsigned char raw[];
    int*   rowIdxS = reinterpret_cast<int*>(raw + SM_IDX_OFF);
    float* ccombS  = reinterpret_cast<float*>(raw + SM_CC_OFF);
    float* Cs      = reinterpret_cast<float*>(raw);   // epilogue, aliases A bufs

    int tid = threadIdx.x;
    int t = blockIdx.x;

    // find (expert, tile) from d_cursor (== per-expert counts after K1)
    int e = -1, tileIn = 0, nrows = 0;
    {
        int ts = 0;
#pragma unroll
        for (int i = 0; i < E_N; i++) {
            int c = d_cursor[i];
            int tiles = (c + TILE_M - 1) >> 7;
            if (e < 0 && t >= ts && t < ts + tiles) {
                e = i; tileIn = t - ts;
                nrows = min(TILE_M, c - tileIn * TILE_M);
            }
            ts += tiles;
        }
        if (e < 0) return;
    }

    if (tid < TILE_M)
        rowIdxS[tid] = d_expertList[e * B_N + tileIn * TILE_M
                                    + ((tid < nrows) ? tid : 0)];
    if (tid < K_N)
        ccombS[tid] = d_ccomb[e * K_N + tid];
    __syncthreads();

    const uint32_t* WbE = d_Wpack + (size_t)e * (D_PAD * K_N);
    uint32_t smem_u32 = (uint32_t)__cvta_generic_to_shared(raw);

    int warp = tid >> 5, lane = tid & 31;
    int g = lane >> 2, tig = lane & 3;
    int mw = warp >> 1, nw = warp & 1;
    int mrow0 = mw * 16, n0 = nw * 32;

    float acc[4][4];
#pragma unroll
    for (int n = 0; n < 4; n++)
#pragma unroll
        for (int q = 0; q < 4; q++) acc[n][q] = 0.f;

    // A producer mapping: 4 threads per row, 2 x 16B each (128 B/row/chunk)
    int arow = tid >> 2, aseg = tid & 3;
    const char* xrowA = reinterpret_cast<const char*>(x)
                      + (size_t)rowIdxS[arow] * X_ROW_BYTES;

    auto issueA = [&](int cb, int buf) {
        uint32_t adst = smem_u32 + buf * A_BUF_BYTES + arow * (A_PITCH * 4);
        int base = cb * 128;
#pragma unroll
        for (int p = 0; p < 2; p++) {
            int off = aseg * 16 + p * 64;
            if (base + off < X_ROW_BYTES)                 // only clips on cb=24
                cp_async16(adst + off, xrowA + base + off);
        }
    };
    auto issueB = [&](int cb, int buf) {
        uint32_t bdst = smem_u32 + SM_B_OFF + buf * B_BUF_BYTES;
        int kk = tid >> 4, n4 = (tid & 15) * 4;
        cp_async16(bdst + (kk * B_PITCH + n4) * 4,
                   WbE + (size_t)cb * (CHUNK_D * K_N) + tid * 4);
    };

    // ---- prologue: chunks 0, 1, 2 ----
    issueA(0, 0); issueB(0, 0); CP_COMMIT();
    issueA(1, 1); issueB(1, 1); CP_COMMIT();
    issueA(2, 2); issueB(2, 2); CP_COMMIT();

    int buf = 0;
    for (int cb = 0; cb < NCHUNK; cb++) {
        const float*    Af = reinterpret_cast<const float*>(raw + buf * A_BUF_BYTES);
        const uint32_t* Bs = reinterpret_cast<const uint32_t*>(raw + SM_B_OFF + buf * B_BUF_BYTES);

        // chunk cb landed when <= (committed_upto - cb) groups remain pending
        int rem = NCHUNK - 1 - cb;
        if (rem >= 2)      CP_WAIT2();
        else if (rem == 1) CP_WAIT1();
        else               CP_WAIT0();
        __syncthreads();                   // visible; MMA_{cb-1} finished

        if (cb + 3 < NCHUNK) {
            int nb = buf + 3; if (nb >= NSTAGE) nb -= NSTAGE;
            issueA(cb + 3, nb);            // safe: MMA_{cb-1} done by this sync
            issueB(cb + 3, nb);
            CP_COMMIT();
        }

        // ---- MMA: 16 rows x 32 cols, 4 k16 steps; pack A frags on the fly ----
#pragma unroll
        for (int ks = 0; ks < KSTEPS; ks++) {
            int kkb = ks * 8;
            uint32_t a[4];
            a[0] = pack_x_x2(Af[(mrow0 + g)     * A_PITCH + kkb + tig]);
            a[1] = pack_x_x2(Af[(mrow0 + 8 + g) * A_PITCH + kkb + tig]);
            a[2] = pack_x_x2(Af[(mrow0 + g)     * A_PITCH + kkb + tig + 4]);
            a[3] = pack_x_x2(Af[(mrow0 + 8 + g) * A_PITCH + kkb + tig + 4]);
#pragma unroll
            for (int nt = 0; nt < 4; nt++) {
                uint32_t b0 = Bs[(kkb + tig)     * B_PITCH + n0 + nt * 8 + g];
                uint32_t b1 = Bs[(kkb + tig + 4) * B_PITCH + n0 + nt * 8 + g];
                mma_bf16(acc[nt], a, b0, b1);
            }
        }
        buf++; if (buf >= NSTAGE) buf = 0;
    }
    __syncthreads();   // all MMAs done before Cs aliases the A buffers

    // ---- epilogue: accums -> smem ----
    {
        int row0 = mrow0 + g;
#pragma unroll
        for (int nt = 0; nt < 4; nt++) {
            int col = n0 + nt * 8 + tig * 2;
            Cs[row0 * C_PITCH + col]           = acc[nt][0];
            Cs[row0 * C_PITCH + col + 1]       = acc[nt][1];
            Cs[(row0 + 8) * C_PITCH + col]     = acc[nt][2];
            Cs[(row0 + 8) * C_PITCH + col + 1] = acc[nt][3];
        }
    }
    __syncthreads();

    // ---- logsumexp per row, scatter to original index ----
    if (tid < TILE_M) {
        const float* crow = &Cs[tid * C_PITCH];
        float mx = -3.4e38f;
#pragma unroll 8
        for (int j = 0; j < K_N; j++) mx = fmaxf(mx, crow[j] + ccombS[j]);
        float s = 0.f;
#pragma unroll 8
        for (int j = 0; j < K_N; j++) s += expf(crow[j] + ccombS[j] - mx);
        float ll = mx + logf(s);
        if (tid < nrows) out[rowIdxS[tid]] = ll;
    }
}

// ============================================================================
extern "C" void kernel_launch(void* const* d_in, const int* in_sizes, int n_in,
                              void* d_out, int out_size) {
    const float* x         = (const float*)d_in[0];
    const float* centroids = (const float*)d_in[1];
    const float* means     = (const float*)d_in[2];
    const float* log_stds  = (const float*)d_in[3];
    const float* logits    = (const float*)d_in[4];
    float* out = (float*)d_out;

    static bool attr_set = false;
    if (!attr_set) {
        cudaFuncSetAttribute(k4_gemm, cudaFuncAttributeMaxDynamicSharedMemorySize,
                             SM_TOTAL_K4);
        attr_set = true;
    }

    k0_prep <<<E_N * K_N, 256>>>(means, log_stds, logits);
    k1_route<<<B_N / (8 * RPW), 256>>>(x, centroids);
    k4_gemm <<<B_N / TILE_M + E_N, 512, SM_TOTAL_K4>>>(x, out);
}

// round 16
// speedup vs baseline: 1.2560x; 1.0463x over previous
#include <cuda_runtime.h>
#include <cuda_bf16.h>
#include <cstdint>

// ============================================================================
// EinetMixture: route each row to nearest centroid (E=8), then compute only
// that expert's Gaussian-leaf log-likelihood (K=64 leaves) + logsumexp.
//
// leaf_ll[b,k] = sum_d ( a[e,k,d]*x^2 + b[e,k,d]*x ) + c[e,k]
// d-reduction = bf16 mma.sync GEMM; K-dim interleaved as (x[d], x^2[d]) pairs
// matching W pairs (bcoef, acoef). A staged in smem as RAW f32 x (cp.async);
// pack (x,x^2)->bf16x2 at fragment-load time.
//
// TWO launches: k01 (route blocks 0..511 || prep blocks 512..711) -> k4.
// ccomb is finalized per-CTA inside k4 from per-chunk csum partials.
// d_cursor is re-zeroed by k4's last block (self-resetting ticket counter).
// ============================================================================

#define B_N 32768
#define D_N 784
#define D_PAD 800             // 25 chunks of 32 d (pad coeffs are zero)
#define E_N 8
#define K_N 64
#define F4_PER_ROW 196        // 784/4
#define X_ROW_BYTES 3136      // 784*4

#define TILE_M 128
#define CHUNK_D 32            // d's per K4 chunk (64 bf16 of K)
#define NCHUNK 25
#define KSTEPS 4              // k16 steps per chunk
#define NSTAGE 4
#define A_PITCH 36            // f32 pitch; frag banks (4g+tig) distinct
#define B_PITCH 72            // u32 pitch; frag banks (8tig+g) distinct
#define C_PITCH 66            // float pitch for epilogue

#define ROUTE_BLOCKS 512      // B_N / 64
#define PREP_BLOCKS  (E_N * NCHUNK)   // 200

#define A_BUF_BYTES (TILE_M * A_PITCH * 4)        // 18432
#define B_BUF_BYTES (CHUNK_D * B_PITCH * 4)       // 9216
#define SM_B_OFF   (NSTAGE * A_BUF_BYTES)         // 73728
#define SM_IDX_OFF (SM_B_OFF + NSTAGE * B_BUF_BYTES)  // 110592
#define SM_CC_OFF  (SM_IDX_OFF + TILE_M * 4)      // 111104
#define SM_LG_OFF  (SM_CC_OFF + K_N * 4)          // 111360
#define SM_TOTAL_K4 (SM_LG_OFF + K_N * 4)         // 111616 (x2 CTAs <= 228KB)

#define LOG_2PI 1.8378770664093453f

// ---------------- device scratch (no allocation allowed) ----------------
__device__ __align__(16) uint32_t d_Wpack[E_N * D_PAD * K_N]; // [e][d][k] bf16x2 (b,a)
__device__ float    d_csumPart[E_N * NCHUNK * K_N];  // per-chunk csum partials
__device__ int      d_cursor[E_N];              // per-expert cursor == final counts
__device__ int      d_expertList[E_N * B_N];    // row indices grouped by expert
__device__ int      d_done = 0;                 // k4 completion ticket (self-reset)

// ---------------- helpers ----------------
__device__ __forceinline__ uint32_t pack_x_x2(float v) {
    __nv_bfloat162 p = __floats2bfloat162_rn(v, v * v);   // lo = x, hi = x^2
    return *reinterpret_cast<uint32_t*>(&p);
}

__device__ __forceinline__ void mma_bf16(float* c, const uint32_t* a,
                                         uint32_t b0, uint32_t b1) {
    asm volatile(
        "mma.sync.aligned.m16n8k16.row.col.f32.bf16.bf16.f32 "
        "{%0,%1,%2,%3}, {%4,%5,%6,%7}, {%8,%9}, {%0,%1,%2,%3};\n"
        : "+f"(c[0]), "+f"(c[1]), "+f"(c[2]), "+f"(c[3])
        : "r"(a[0]), "r"(a[1]), "r"(a[2]), "r"(a[3]), "r"(b0), "r"(b1));
}

__device__ __forceinline__ void cp_async16(uint32_t smem_addr, const void* gptr) {
    asm volatile("cp.async.cg.shared.global [%0], [%1], 16;\n"
                 :: "r"(smem_addr), "l"(gptr));
}
#define CP_COMMIT() asm volatile("cp.async.commit_group;\n" ::: "memory")
#define CP_WAIT0()  asm volatile("cp.async.wait_group 0;\n" ::: "memory")
#define CP_WAIT1()  asm volatile("cp.async.wait_group 1;\n" ::: "memory")
#define CP_WAIT2()  asm volatile("cp.async.wait_group 2;\n" ::: "memory")

// ============================================================================
// K01: merged prep + route. 256 threads.
//   blocks [0, 512): routing + scatter (one warp per 8 rows).
//   blocks [512, 712): weight prep, one (expert, 32-d chunk) per block,
//     smem-transposed so d_Wpack writes are fully coalesced (8KB contiguous).
// ============================================================================
#define RPW 8
__global__ void __launch_bounds__(256) k01_prep_route(
        const float* __restrict__ x,
        const float* __restrict__ centroids,
        const float* __restrict__ means,
        const float* __restrict__ log_stds) {
    int tid = threadIdx.x;

    if (blockIdx.x >= ROUTE_BLOCKS) {
        // ---------------- PREP block: (e, chunk cb) -> [32 d][64 k] tile ----
        __shared__ uint32_t tile[CHUNK_D * K_N];   // 8KB
        __shared__ float red4[256];                // red4[k*4 + seg]
        int pb = blockIdx.x - ROUTE_BLOCKS;
        int e  = pb / NCHUNK;
        int cb = pb - e * NCHUNK;

        int k   = tid >> 2;          // 0..63
        int seg = tid & 3;           // 8-d sub-block
        int d0  = cb * CHUNK_D + seg * 8;

        const float* mrow = means    + (size_t)(e * K_N + k) * D_N + d0;
        const float* lrow = log_stds + (size_t)(e * K_N + k) * D_N + d0;

        float4 m0, m1, l0, l1;
        bool valid = d0 < D_N;       // whole 8-d block valid (d0 multiple of 8)
        if (valid) {
            m0 = *reinterpret_cast<const float4*>(mrow);
            m1 = *reinterpret_cast<const float4*>(mrow + 4);
            l0 = *reinterpret_cast<const float4*>(lrow);
            l1 = *reinterpret_cast<const float4*>(lrow + 4);
        } else {
            m0 = m1 = l0 = l1 = make_float4(0.f, 0.f, 0.f, 0.f);
        }
        float mv[8] = {m0.x, m0.y, m0.z, m0.w, m1.x, m1.y, m1.z, m1.w};
        float lv[8] = {l0.x, l0.y, l0.z, l0.w, l1.x, l1.y, l1.z, l1.w};

        float csum = 0.f;
#pragma unroll
        for (int j = 0; j < 8; j++) {
            uint32_t pk = 0;
            if (valid) {
                float iv = __expf(-2.f * lv[j]);
                float bc = mv[j] * iv;
                csum += -0.5f * mv[j] * mv[j] * iv - lv[j];
                __nv_bfloat162 p = __floats2bfloat162_rn(bc, -0.5f * iv); // lo=b, hi=a
                pk = *reinterpret_cast<uint32_t*>(&p);
            }
            tile[(seg * 8 + j) * K_N + k] = pk;
        }
        red4[k * 4 + seg] = csum;
        __syncthreads();

        // coalesced 8KB write: thread -> 2 x uint4 at contiguous offsets
        size_t baseW = ((size_t)(e * D_PAD + cb * CHUNK_D)) << 6;
        uint4* dst = reinterpret_cast<uint4*>(d_Wpack + baseW);
        const uint4* src = reinterpret_cast<const uint4*>(tile);
        dst[tid * 2]     = src[tid * 2];
        dst[tid * 2 + 1] = src[tid * 2 + 1];

        if (tid < K_N) {
            float s = red4[tid * 4] + red4[tid * 4 + 1]
                    + red4[tid * 4 + 2] + red4[tid * 4 + 3];
            d_csumPart[(e * NCHUNK + cb) * K_N + tid] = s;
        }
        return;
    }

    // ---------------- ROUTE block ----------------
    __shared__ float4 cent[E_N * F4_PER_ROW];   // 25088 B
    __shared__ float  cnormS[E_N];
    __shared__ int hist[E_N];
    __shared__ int base[E_N];
    int warp = tid >> 5, lane = tid & 31;
    if (tid < E_N) hist[tid] = 0;
    const float4* c4 = reinterpret_cast<const float4*>(centroids);
    for (int j = tid; j < E_N * F4_PER_ROW; j += 256) cent[j] = c4[j];
    __syncthreads();

    // centroid norms: warp w handles expert w
    {
        float cn = 0.f;
        for (int j = lane; j < F4_PER_ROW; j += 32) {
            float4 cv = cent[warp * F4_PER_ROW + j];
            cn += cv.x * cv.x + cv.y * cv.y + cv.z * cv.z + cv.w * cv.w;
        }
#pragma unroll
        for (int o = 16; o; o >>= 1) cn += __shfl_xor_sync(0xffffffffu, cn, o);
        if (lane == 0) cnormS[warp] = cn;
    }
    __syncthreads();

    int b0 = blockIdx.x * (8 * RPW) + warp * RPW;
    const float4* x4 = reinterpret_cast<const float4*>(x) + (size_t)b0 * F4_PER_ROW;

    float dot[RPW][E_N];
#pragma unroll
    for (int r = 0; r < RPW; r++)
#pragma unroll
        for (int e = 0; e < E_N; e++) dot[r][e] = 0.f;

    for (int j = lane; j < F4_PER_ROW; j += 32) {
        float4 xv[RPW];
#pragma unroll
        for (int r = 0; r < RPW; r++) xv[r] = x4[(size_t)r * F4_PER_ROW + j];
#pragma unroll
        for (int e = 0; e < E_N; e++) {
            float4 cv = cent[e * F4_PER_ROW + j];
#pragma unroll
            for (int r = 0; r < RPW; r++)
                dot[r][e] += xv[r].x * cv.x + xv[r].y * cv.y
                           + xv[r].z * cv.z + xv[r].w * cv.w;
        }
    }
#pragma unroll
    for (int r = 0; r < RPW; r++)
#pragma unroll
        for (int e = 0; e < E_N; e++)
#pragma unroll
            for (int o = 16; o; o >>= 1)
                dot[r][e] += __shfl_xor_sync(0xffffffffu, dot[r][e], o);

    int bi[RPW], rk[RPW];
    if (lane == 0) {
#pragma unroll
        for (int r = 0; r < RPW; r++) {
            float best = 3.4e38f;
            int sel = 0;
#pragma unroll
            for (int e = 0; e < E_N; e++) {
                float s = cnormS[e] - 2.f * dot[r][e];
                if (s < best) { best = s; sel = e; }   // first-min == argmin
            }
            bi[r] = sel;
            rk[r] = atomicAdd(&hist[sel], 1);          // block-local rank
        }
    }
    __syncthreads();
    if (tid < E_N)
        base[tid] = hist[tid] ? atomicAdd(&d_cursor[tid], hist[tid]) : 0;
    __syncthreads();
    if (lane == 0) {
#pragma unroll
        for (int r = 0; r < RPW; r++)
            d_expertList[bi[r] * B_N + base[bi[r]] + rk[r]] = b0 + r;
    }
}

// ============================================================================
// K4: grouped GEMM, 512 threads (16 warps), warp tile 16x32 (8m x 2n),
// 4-stage cp.async pipeline, one sync/chunk. A staged as RAW f32 x; pack
// (x,x^2)->bf16x2 at fragment-load. Prologue reconstructs ccomb from the
// csum partials + log_softmax(logits). Last-finishing block zeroes d_cursor
// for the next replay (ticket counter wraps to 0 -> deterministic graph).
// ============================================================================
__global__ void __launch_bounds__(512, 2) k4_gemm(const float* __restrict__ x,
                                                  const float* __restrict__ logits,
                                                  float* __restrict__ out) {
    extern __shared__ __align__(16) unsigned char raw[];
    int*   rowIdxS = reinterpret_cast<int*>(raw + SM_IDX_OFF);
    float* ccombS  = reinterpret_cast<float*>(raw + SM_CC_OFF);
    float* lgS     = reinterpret_cast<float*>(raw + SM_LG_OFF);
    float* Cs      = reinterpret_cast<float*>(raw);   // epilogue, aliases A bufs

    int tid = threadIdx.x;
    int t = blockIdx.x;

    // find (expert, tile) from d_cursor (== per-expert counts after K01)
    int e = -1, tileIn = 0, nrows = 0;
    {
        int ts = 0;
#pragma unroll
        for (int i = 0; i < E_N; i++) {
            int c = d_cursor[i];
            int tiles = (c + TILE_M - 1) >> 7;
            if (e < 0 && t >= ts && t < ts + tiles) {
                e = i; tileIn = t - ts;
                nrows = min(TILE_M, c - tileIn * TILE_M);
            }
            ts += tiles;
        }
    }
    if (e < 0) {   // beyond last tile: still participate in the ticket
        if (tid == 0) {
            __threadfence();
            if (atomicAdd(&d_done, 1) == gridDim.x - 1) {
#pragma unroll
                for (int i = 0; i < E_N; i++) d_cursor[i] = 0;
                __threadfence();
                d_done = 0;
            }
        }
        return;
    }

    // ---- prologue: row indices + ccomb reconstruction ----
    if (tid < TILE_M)
        rowIdxS[tid] = d_expertList[e * B_N + tileIn * TILE_M
                                    + ((tid < nrows) ? tid : 0)];
    float csk = 0.f;
    if (tid < K_N) {
        lgS[tid] = logits[e * K_N + tid];
        const float* p = d_csumPart + (size_t)e * (NCHUNK * K_N) + tid;
#pragma unroll
        for (int c = 0; c < NCHUNK; c++) csk += p[c * K_N];
    }
    __syncthreads();
    if (tid < K_N) {
        float mx = lgS[0];
#pragma unroll 8
        for (int j = 1; j < K_N; j++) mx = fmaxf(mx, lgS[j]);
        float s = 0.f;
#pragma unroll 8
        for (int j = 0; j < K_N; j++) s += __expf(lgS[j] - mx);
        float lse = mx + logf(s);
        ccombS[tid] = csk - 0.5f * (float)D_N * LOG_2PI + lgS[tid] - lse;
    }
    __syncthreads();

    const uint32_t* WbE = d_Wpack + (size_t)e * (D_PAD * K_N);
    uint32_t smem_u32 = (uint32_t)__cvta_generic_to_shared(raw);

    int warp = tid >> 5, lane = tid & 31;
    int g = lane >> 2, tig = lane & 3;
    int mw = warp >> 1, nw = warp & 1;
    int mrow0 = mw * 16, n0 = nw * 32;

    float acc[4][4];
#pragma unroll
    for (int n = 0; n < 4; n++)
#pragma unroll
        for (int q = 0; q < 4; q++) acc[n][q] = 0.f;

    // A producer mapping: 4 threads per row, 2 x 16B each (128 B/row/chunk)
    int arow = tid >> 2, aseg = tid & 3;
    const char* xrowA = reinterpret_cast<const char*>(x)
                      + (size_t)rowIdxS[arow] * X_ROW_BYTES;

    auto issueA = [&](int cb, int buf) {
        uint32_t adst = smem_u32 + buf * A_BUF_BYTES + arow * (A_PITCH * 4);
        int base = cb * 128;
#pragma unroll
        for (int p = 0; p < 2; p++) {
            int off = aseg * 16 + p * 64;
            if (base + off < X_ROW_BYTES)                 // only clips on cb=24
                cp_async16(adst + off, xrowA + base + off);
        }
    };
    auto issueB = [&](int cb, int buf) {
        uint32_t bdst = smem_u32 + SM_B_OFF + buf * B_BUF_BYTES;
        int kk = tid >> 4, n4 = (tid & 15) * 4;
        cp_async16(bdst + (kk * B_PITCH + n4) * 4,
                   WbE + (size_t)cb * (CHUNK_D * K_N) + tid * 4);
    };

    // ---- prologue: chunks 0, 1, 2 ----
    issueA(0, 0); issueB(0, 0); CP_COMMIT();
    issueA(1, 1); issueB(1, 1); CP_COMMIT();
    issueA(2, 2); issueB(2, 2); CP_COMMIT();

    int buf = 0;
    for (int cb = 0; cb < NCHUNK; cb++) {
        const float*    Af = reinterpret_cast<const float*>(raw + buf * A_BUF_BYTES);
        const uint32_t* Bs = reinterpret_cast<const uint32_t*>(raw + SM_B_OFF + buf * B_BUF_BYTES);

        int rem = NCHUNK - 1 - cb;
        if (rem >= 2)      CP_WAIT2();
        else if (rem == 1) CP_WAIT1();
        else               CP_WAIT0();
        __syncthreads();                   // visible; MMA_{cb-1} finished

        if (cb + 3 < NCHUNK) {
            int nb = buf + 3; if (nb >= NSTAGE) nb -= NSTAGE;
            issueA(cb + 3, nb);            // safe: MMA_{cb-1} done by this sync
            issueB(cb + 3, nb);
            CP_COMMIT();
        }

        // ---- MMA: 16 rows x 32 cols, 4 k16 steps; pack A frags on the fly ----
#pragma unroll
        for (int ks = 0; ks < KSTEPS; ks++) {
            int kkb = ks * 8;
            uint32_t a[4];
            a[0] = pack_x_x2(Af[(mrow0 + g)     * A_PITCH + kkb + tig]);
            a[1] = pack_x_x2(Af[(mrow0 + 8 + g) * A_PITCH + kkb + tig]);
            a[2] = pack_x_x2(Af[(mrow0 + g)     * A_PITCH + kkb + tig + 4]);
            a[3] = pack_x_x2(Af[(mrow0 + 8 + g) * A_PITCH + kkb + tig + 4]);
#pragma unroll
            for (int nt = 0; nt < 4; nt++) {
                uint32_t b0 = Bs[(kkb + tig)     * B_PITCH + n0 + nt * 8 + g];
                uint32_t b1 = Bs[(kkb + tig + 4) * B_PITCH + n0 + nt * 8 + g];
                mma_bf16(acc[nt], a, b0, b1);
            }
        }
        buf++; if (buf >= NSTAGE) buf = 0;
    }
    __syncthreads();   // all MMAs done before Cs aliases the A buffers

    // ---- epilogue: accums -> smem ----
    {
        int row0 = mrow0 + g;
#pragma unroll
        for (int nt = 0; nt < 4; nt++) {
            int col = n0 + nt * 8 + tig * 2;
            Cs[row0 * C_PITCH + col]           = acc[nt][0];
            Cs[row0 * C_PITCH + col + 1]       = acc[nt][1];
            Cs[(row0 + 8) * C_PITCH + col]     = acc[nt][2];
            Cs[(row0 + 8) * C_PITCH + col + 1] = acc[nt][3];
        }
    }
    __syncthreads();

    // ---- logsumexp per row, scatter to original index ----
    if (tid < TILE_M) {
        const float* crow = &Cs[tid * C_PITCH];
        float mx = -3.4e38f;
#pragma unroll 8
        for (int j = 0; j < K_N; j++) mx = fmaxf(mx, crow[j] + ccombS[j]);
        float s = 0.f;
#pragma unroll 8
        for (int j = 0; j < K_N; j++) s += expf(crow[j] + ccombS[j] - mx);
        float ll = mx + logf(s);
        if (tid < nrows) out[rowIdxS[tid]] = ll;
    }

    // ---- completion ticket: last block resets cursors for next replay ----
    if (tid == 0) {
        __threadfence();
        if (atomicAdd(&d_done, 1) == gridDim.x - 1) {
#pragma unroll
            for (int i = 0; i < E_N; i++) d_cursor[i] = 0;
            __threadfence();
            d_done = 0;
        }
    }
}

// ============================================================================
extern "C" void kernel_launch(void* const* d_in, const int* in_sizes, int n_in,
                              void* d_out, int out_size) {
    const float* x         = (const float*)d_in[0];
    const float* centroids = (const float*)d_in[1];
    const float* means     = (const float*)d_in[2];
    const float* log_stds  = (const float*)d_in[3];
    const float* logits    = (const float*)d_in[4];
    float* out = (float*)d_out;

    static bool attr_set = false;
    if (!attr_set) {
        cudaFuncSetAttribute(k4_gemm, cudaFuncAttributeMaxDynamicSharedMemorySize,
                             SM_TOTAL_K4);
        attr_set = true;
    }

    k01_prep_route<<<ROUTE_BLOCKS + PREP_BLOCKS, 256>>>(x, centroids, means, log_stds);
    k4_gemm<<<B_N / TILE_M + E_N, 512, SM_TOTAL_K4>>>(x, logits, out);
}